// round 1
// baseline (speedup 1.0000x reference)
#include <cuda_runtime.h>
#include <cuda_bf16.h>
#include <math.h>
#include <stdint.h>

// ---------------- constants ----------------
#define N_ROIS   22500
#define IMGSZ    800.0f
#define MIN_SIZE 16.0f
#define PRE_NMS  2000
#define POST_NMS 128
#define IOU_TH   0.7f
#define FEAT_C   512
#define FEAT_HW  50
#define OUTSZ    7
#define D_IN     25088   // 512*7*7
#define D_H      4096
#define NC       21
#define SORT_N   4096

// out layout: cls [128*21] @0, deltas [128*84] @2688, rois_kept [128*4] @13440
#define OFF_DELTAS 2688
#define OFF_ROIS   13440

// ---------------- device scratch (no allocs allowed) ----------------
__device__ float              g_featT[FEAT_HW * FEAT_HW * FEAT_C];   // [p][c]
__device__ float              g_pooled[POST_NMS * D_IN];             // [r][s*512+c]
__device__ float              g_h1[POST_NMS * D_H];
__device__ float              g_h2[POST_NMS * D_H];
__device__ unsigned long long g_keys[N_ROIS];
__device__ int                g_hist[65536];
__device__ int                g_cnt;
__device__ int                g_threshBin;
__device__ unsigned long long g_cand[SORT_N];
__device__ float              g_boxes[PRE_NMS * 4];
__device__ unsigned long long g_mask[PRE_NMS * 32];
__device__ int                g_keep[POST_NMS];
__device__ float              g_roisKept[POST_NMS * 4];

// ---------------- stage 0: zero hist ----------------
__global__ void zeroK() {
    int i = blockIdx.x * blockDim.x + threadIdx.x;
    if (i < 65536) g_hist[i] = 0;
    if (i == 0) g_cnt = 0;
}

// ---------------- stage 1: score + sortable key + histogram ----------------
__global__ void scoreK(const float* __restrict__ rois, const float* __restrict__ logits) {
    int i = blockIdx.x * blockDim.x + threadIdx.x;
    if (i >= N_ROIS) return;
    float y1 = fminf(fmaxf(rois[i * 4 + 0], 0.f), IMGSZ);
    float x1 = fminf(fmaxf(rois[i * 4 + 1], 0.f), IMGSZ);
    float y2 = fminf(fmaxf(rois[i * 4 + 2], 0.f), IMGSZ);
    float x2 = fminf(fmaxf(rois[i * 4 + 3], 0.f), IMGSZ);
    bool valid = ((y2 - y1) >= MIN_SIZE) && ((x2 - x1) >= MIN_SIZE);
    float l0 = logits[i * 2 + 0], l1 = logits[i * 2 + 1];
    float m = fmaxf(l0, l1);
    float e0 = expf(l0 - m), e1 = expf(l1 - m);
    float score = valid ? (e1 / (e0 + e1)) : -1.0f;
    unsigned b = __float_as_uint(score);
    unsigned key = (b & 0x80000000u) ? ~b : (b | 0x80000000u);
    g_keys[i] = ((unsigned long long)key << 32) | (unsigned)(~(unsigned)i);
    atomicAdd(&g_hist[key >> 16], 1);
}

// ---------------- stage 2: find threshold bin (cnt_ge[T] >= 2000 > cnt_ge[T+1]) ----------------
__global__ void threshK() {
    __shared__ int suf[1024];
    int t = threadIdx.x;
    int s = 0;
    for (int b = t * 64; b < t * 64 + 64; b++) s += g_hist[b];
    suf[t] = s;
    __syncthreads();
    for (int off = 1; off < 1024; off <<= 1) {
        int v = (t + off < 1024) ? suf[t + off] : 0;
        __syncthreads();
        suf[t] += v;
        __syncthreads();
    }
    int run = (t + 1 < 1024) ? suf[t + 1] : 0;  // count of bins >= (t+1)*64
    for (int b = t * 64 + 63; b >= t * 64; b--) {
        int h = g_hist[b];
        int ge = run + h;
        if (ge >= PRE_NMS && run < PRE_NMS) g_threshBin = b;
        run = ge;
    }
}

// ---------------- stage 3: compact candidates ----------------
__global__ void compactK() {
    int i = blockIdx.x * blockDim.x + threadIdx.x;
    if (i >= N_ROIS) return;
    unsigned long long k = g_keys[i];
    int bin = (int)(k >> 48);
    if (bin >= g_threshBin) {
        int pos = atomicAdd(&g_cnt, 1);
        if (pos < SORT_N) g_cand[pos] = k;
    }
}

// ---------------- stage 4: single-block bitonic sort (descending), emit top-2000 boxes ----------------
__global__ void sortK(const float* __restrict__ rois) {
    __shared__ unsigned long long s[SORT_N];
    int tid = threadIdx.x;
    int cnt = g_cnt; if (cnt > SORT_N) cnt = SORT_N;
    for (int i = tid; i < SORT_N; i += 1024) s[i] = (i < cnt) ? g_cand[i] : 0ULL;
    __syncthreads();
    for (int k = 2; k <= SORT_N; k <<= 1) {
        for (int j = k >> 1; j > 0; j >>= 1) {
            for (int i = tid; i < SORT_N; i += 1024) {
                int l = i ^ j;
                if (l > i) {
                    unsigned long long a = s[i], b = s[l];
                    bool desc = ((i & k) == 0);
                    bool sw = desc ? (a < b) : (a > b);
                    if (sw) { s[i] = b; s[l] = a; }
                }
            }
            __syncthreads();
        }
    }
    for (int r = tid; r < PRE_NMS; r += 1024) {
        int idx = (int)(~(unsigned)s[r]);
        float y1 = fminf(fmaxf(rois[idx * 4 + 0], 0.f), IMGSZ);
        float x1 = fminf(fmaxf(rois[idx * 4 + 1], 0.f), IMGSZ);
        float y2 = fminf(fmaxf(rois[idx * 4 + 2], 0.f), IMGSZ);
        float x2 = fminf(fmaxf(rois[idx * 4 + 3], 0.f), IMGSZ);
        g_boxes[r * 4 + 0] = y1;
        g_boxes[r * 4 + 1] = x1;
        g_boxes[r * 4 + 2] = y2;
        g_boxes[r * 4 + 3] = x2;
    }
}

// ---------------- stage 5: NMS IoU bitmask ----------------
__global__ void nmsMaskK() {
    __shared__ float col[64][4];
    int t = threadIdx.x;
    int cbase = blockIdx.x * 64;
    if (cbase + t < PRE_NMS) {
        col[t][0] = g_boxes[(cbase + t) * 4 + 0];
        col[t][1] = g_boxes[(cbase + t) * 4 + 1];
        col[t][2] = g_boxes[(cbase + t) * 4 + 2];
        col[t][3] = g_boxes[(cbase + t) * 4 + 3];
    } else {
        col[t][0] = col[t][1] = col[t][2] = col[t][3] = 0.f;
    }
    __syncthreads();
    int row = blockIdx.y * 64 + t;
    if (row >= PRE_NMS) return;
    float ry1 = g_boxes[row * 4 + 0], rx1 = g_boxes[row * 4 + 1];
    float ry2 = g_boxes[row * 4 + 2], rx2 = g_boxes[row * 4 + 3];
    float ra = (ry2 - ry1) * (rx2 - rx1);
    unsigned long long bits = 0;
    #pragma unroll 8
    for (int j = 0; j < 64; j++) {
        int c = cbase + j;
        if (c >= PRE_NMS || c == row) continue;
        float ca = (col[j][2] - col[j][0]) * (col[j][3] - col[j][1]);
        float yy1 = fmaxf(ry1, col[j][0]);
        float xx1 = fmaxf(rx1, col[j][1]);
        float yy2 = fminf(ry2, col[j][2]);
        float xx2 = fminf(rx2, col[j][3]);
        float inter = fmaxf(yy2 - yy1, 0.f) * fmaxf(xx2 - xx1, 0.f);
        float iou = inter / (ra + ca - inter + 1e-9f);
        if (iou > IOU_TH) bits |= (1ull << j);
    }
    g_mask[row * 32 + blockIdx.x] = bits;
}

// ---------------- stage 6: sequential NMS scan (1 warp), emit 128 kept ----------------
__global__ void nmsScanK(float* __restrict__ out) {
    int lane = threadIdx.x;  // 32 threads
    __shared__ unsigned char keptFlag[PRE_NMS];
    for (int i = lane; i < PRE_NMS; i += 32) keptFlag[i] = 0;
    __syncwarp();
    unsigned long long remv = 0;
    int cnt = 0;
    for (int i = 0; i < PRE_NMS; i++) {
        unsigned long long w = __shfl_sync(0xffffffffu, remv, i >> 6);
        if (!((w >> (i & 63)) & 1ull)) {
            remv |= g_mask[i * 32 + lane];
            if (cnt < POST_NMS && lane == 0) { g_keep[cnt] = i; keptFlag[i] = 1; }
            cnt++;
            if (cnt == POST_NMS) break;
        }
    }
    __syncwarp();
    if (lane == 0 && cnt < POST_NMS) {
        // rare fallback: pad with smallest non-kept indices, merged sorted (matches rank_score ties)
        int extras[POST_NMS]; int ne = 0;
        for (int i = 0; i < PRE_NMS && ne < POST_NMS - cnt; i++)
            if (!keptFlag[i]) extras[ne++] = i;
        int merged[POST_NMS]; int a = 0, b = 0;
        for (int o = 0; o < POST_NMS; o++) {
            int va = (a < cnt) ? g_keep[a] : 0x7fffffff;
            int vb = (b < ne) ? extras[b] : 0x7fffffff;
            if (va < vb) { merged[o] = va; a++; } else { merged[o] = vb; b++; }
        }
        for (int o = 0; o < POST_NMS; o++) g_keep[o] = merged[o];
    }
    __syncwarp();
    for (int r = lane; r < POST_NMS; r += 32) {
        int idx = g_keep[r];
        #pragma unroll
        for (int j = 0; j < 4; j++) {
            float v = g_boxes[idx * 4 + j];
            g_roisKept[r * 4 + j] = v;
            out[OFF_ROIS + r * 4 + j] = v;
        }
    }
}

// ---------------- stage 7: transpose features CHW -> HWC ----------------
__global__ void transposeK(const float* __restrict__ feat) {
    __shared__ float tile[32][33];
    int p = blockIdx.x * 32 + threadIdx.x;  // spatial
    int c = blockIdx.y * 32 + threadIdx.y;  // channel
    #pragma unroll
    for (int j = 0; j < 32; j += 8)
        if (p < 2500 && (c + j) < FEAT_C)
            tile[threadIdx.y + j][threadIdx.x] = feat[(c + j) * 2500 + p];
    __syncthreads();
    int c2 = blockIdx.y * 32 + threadIdx.x;
    int p2 = blockIdx.x * 32 + threadIdx.y;
    #pragma unroll
    for (int j = 0; j < 32; j += 8)
        if (c2 < FEAT_C && (p2 + j) < 2500)
            g_featT[(p2 + j) * FEAT_C + c2] = tile[threadIdx.x][threadIdx.y + j];
}

// ---------------- stage 8: ROI align ----------------
__global__ void roiAlignK() {
    int r = blockIdx.x;
    __shared__ float box[4];
    __shared__ int sy0[14], sy1[14], sx0[14], sx1[14];
    __shared__ float sly[14], slx[14];
    int t = threadIdx.x;  // 256
    if (t < 4) box[t] = g_roisKept[r * 4 + t] * (1.0f / 16.0f);
    __syncthreads();
    if (t < 28) {
        int d = t / 14, g = t % 14;
        float c1 = d ? box[1] : box[0];
        float c2 = d ? box[3] : box[2];
        float bsz = fmaxf(c2 - c1, 1.0f) * (1.0f / 7.0f);
        float gg = ((float)g + 0.5f) * 0.5f;
        float s = c1 + gg * bsz;
        s = fminf(fmaxf(s, 0.0f), 49.0f);
        float s0 = floorf(s);
        int i0 = (int)s0;
        int i1 = min(i0 + 1, 49);
        float l = s - s0;
        if (d == 0) { sy0[g] = i0; sy1[g] = i1; sly[g] = l; }
        else        { sx0[g] = i0; sx1[g] = i1; slx[g] = l; }
    }
    __syncthreads();
    float* outr = g_pooled + r * D_IN;
    for (int c = t; c < FEAT_C; c += 256) {
        #pragma unroll
        for (int oy = 0; oy < 7; oy++) {
            #pragma unroll
            for (int ox = 0; ox < 7; ox++) {
                float acc = 0.f;
                #pragma unroll
                for (int sy = 0; sy < 2; sy++) {
                    #pragma unroll
                    for (int sx = 0; sx < 2; sx++) {
                        int i = oy * 2 + sy, j = ox * 2 + sx;
                        int y0 = sy0[i], y1 = sy1[i], x0 = sx0[j], x1 = sx1[j];
                        float ly = sly[i], lx = slx[j];
                        const float* f = g_featT;
                        float v00 = f[(y0 * 50 + x0) * FEAT_C + c];
                        float v01 = f[(y0 * 50 + x1) * FEAT_C + c];
                        float v10 = f[(y1 * 50 + x0) * FEAT_C + c];
                        float v11 = f[(y1 * 50 + x1) * FEAT_C + c];
                        acc += (1.f - ly) * ((1.f - lx) * v00 + lx * v01)
                             + ly * ((1.f - lx) * v10 + lx * v11);
                    }
                }
                outr[(oy * 7 + ox) * FEAT_C + c] = acc * 0.25f;
            }
        }
    }
}

// ---------------- stage 9: tiled fp32 GEMM  C[M,N] = A[M,K] @ B[K,N] + bias ----------------
// PERM=1: B row index for logical k is ((k%512)*49 + k/512)  (undo pooled layout permutation)
template <int PERM>
__global__ __launch_bounds__(256) void gemmK(
    const float* __restrict__ A, const float* __restrict__ B,
    const float* __restrict__ bias, float* __restrict__ C,
    int M, int N, int K)
{
    __shared__ float As[16][68];
    __shared__ float Bs[16][68];
    int bn = blockIdx.x * 64, bm = blockIdx.y * 64;
    int tid = threadIdx.x;
    int tx = tid & 15, ty = tid >> 4;
    float acc[4][4] = {};
    for (int k0 = 0; k0 < K; k0 += 16) {
        #pragma unroll
        for (int e = 0; e < 4; e++) {
            int flat = tid + e * 256;
            int m = flat >> 4, kk = flat & 15;
            int gm = bm + m;
            As[kk][m] = (gm < M) ? A[gm * K + (k0 + kk)] : 0.0f;
        }
        #pragma unroll
        for (int e = 0; e < 4; e++) {
            int flat = tid + e * 256;
            int kk = flat >> 6, n = flat & 63;
            int gk = k0 + kk, gn = bn + n;
            int row = PERM ? ((gk & 511) * 49 + (gk >> 9)) : gk;
            Bs[kk][n] = (gn < N) ? B[row * N + gn] : 0.0f;
        }
        __syncthreads();
        #pragma unroll
        for (int kk = 0; kk < 16; kk++) {
            float a[4], b[4];
            #pragma unroll
            for (int i = 0; i < 4; i++) a[i] = As[kk][ty * 4 + i];
            #pragma unroll
            for (int j = 0; j < 4; j++) b[j] = Bs[kk][tx * 4 + j];
            #pragma unroll
            for (int i = 0; i < 4; i++)
                #pragma unroll
                for (int j = 0; j < 4; j++)
                    acc[i][j] = fmaf(a[i], b[j], acc[i][j]);
        }
        __syncthreads();
    }
    #pragma unroll
    for (int i = 0; i < 4; i++) {
        int gm = bm + ty * 4 + i;
        if (gm >= M) continue;
        #pragma unroll
        for (int j = 0; j < 4; j++) {
            int gn = bn + tx * 4 + j;
            if (gn < N) C[gm * N + gn] = acc[i][j] + bias[gn];
        }
    }
}

// ---------------- launcher ----------------
extern "C" void kernel_launch(void* const* d_in, const int* in_sizes, int n_in,
                              void* d_out, int out_size)
{
    const float* features = (const float*)d_in[0];
    const float* rois     = (const float*)d_in[1];
    const float* logits   = (const float*)d_in[2];
    const float* W1 = (const float*)d_in[3];
    const float* b1 = (const float*)d_in[4];
    const float* W2 = (const float*)d_in[5];
    const float* b2 = (const float*)d_in[6];
    const float* Wc = (const float*)d_in[7];
    const float* bc = (const float*)d_in[8];
    const float* Wd = (const float*)d_in[9];
    const float* bd = (const float*)d_in[10];
    float* out = (float*)d_out;

    float* h1; cudaGetSymbolAddress((void**)&h1, g_h1);
    float* h2; cudaGetSymbolAddress((void**)&h2, g_h2);
    float* pooled; cudaGetSymbolAddress((void**)&pooled, g_pooled);

    zeroK<<<64, 1024>>>();
    scoreK<<<(N_ROIS + 255) / 256, 256>>>(rois, logits);
    threshK<<<1, 1024>>>();
    compactK<<<(N_ROIS + 255) / 256, 256>>>();
    sortK<<<1, 1024>>>(rois);
    nmsMaskK<<<dim3(32, 32), 64>>>();
    nmsScanK<<<1, 32>>>(out);
    transposeK<<<dim3(79, 16), dim3(32, 8)>>>(features);
    roiAlignK<<<POST_NMS, 256>>>();

    // FC1: [128,25088] @ W1[25088,4096] + b1   (permuted k)
    gemmK<1><<<dim3(D_H / 64, 2), 256>>>(pooled, W1, b1, h1, POST_NMS, D_H, D_IN);
    // FC2
    gemmK<0><<<dim3(D_H / 64, 2), 256>>>(h1, W2, b2, h2, POST_NMS, D_H, D_H);
    // heads
    gemmK<0><<<dim3(1, 2), 256>>>(h2, Wc, bc, out, POST_NMS, NC, D_H);
    gemmK<0><<<dim3(2, 2), 256>>>(h2, Wd, bd, out + OFF_DELTAS, POST_NMS, NC * 4, D_H);
}

// round 4
// speedup vs baseline: 5.0187x; 5.0187x over previous
#include <cuda_runtime.h>
#include <cuda_bf16.h>
#include <math.h>
#include <stdint.h>

// ---------------- constants ----------------
#define N_ROIS   22500
#define IMGSZ    800.0f
#define MIN_SIZE 16.0f
#define PRE_NMS  2000
#define POST_NMS 128
#define IOU_TH   0.7f
#define FEAT_C   512
#define FEAT_HW  50
#define D_IN     25088   // 512*7*7
#define D_H      4096
#define NC       21
#define SORT_N   4096

#define OFF_DELTAS 2688
#define OFF_ROIS   13440

// ---------------- device scratch ----------------
__device__ float              g_featT[FEAT_HW * FEAT_HW * FEAT_C];
__device__ float              g_pooled[POST_NMS * D_IN];
__device__ __align__(16) __nv_bfloat16 g_A1h[POST_NMS * D_IN];
__device__ __align__(16) __nv_bfloat16 g_A1l[POST_NMS * D_IN];
__device__ __align__(16) __nv_bfloat16 g_A2h[POST_NMS * D_H];
__device__ __align__(16) __nv_bfloat16 g_A2l[POST_NMS * D_H];
__device__ float              g_part[8 * POST_NMS * D_H];   // split-K partials (16MB)
__device__ float              g_h2[POST_NMS * D_H];
__device__ unsigned long long g_keys[N_ROIS];
__device__ int                g_hist[65536];
__device__ int                g_cnt;
__device__ int                g_threshBin;
__device__ unsigned long long g_cand[SORT_N];
__device__ float              g_boxes[PRE_NMS * 4];
__device__ unsigned long long g_mask[PRE_NMS * 32];
__device__ int                g_keep[POST_NMS];
__device__ float              g_roisKept[POST_NMS * 4];

// ================= helpers =================
__device__ __forceinline__ uint32_t smem_u32(const void* p) {
    uint32_t a;
    asm("{ .reg .u64 t; cvta.to.shared.u64 t, %1; cvt.u32.u64 %0, t; }" : "=r"(a) : "l"(p));
    return a;
}
__device__ __forceinline__ void sts64(uint32_t a, uint32_t w0, uint32_t w1) {
    asm volatile("st.shared.v2.b32 [%0], {%1,%2};" :: "r"(a), "r"(w0), "r"(w1) : "memory");
}
__device__ __forceinline__ void sts128(uint32_t a, uint4 v) {
    asm volatile("st.shared.v4.b32 [%0], {%1,%2,%3,%4};"
                 :: "r"(a), "r"(v.x), "r"(v.y), "r"(v.z), "r"(v.w) : "memory");
}
__device__ __forceinline__ uint32_t bfpack(float lo, float hi) {
    uint32_t r;
    asm("cvt.rn.bf16x2.f32 %0, %1, %2;" : "=r"(r) : "f"(hi), "f"(lo));
    return r;
}
__device__ __forceinline__ void ldsm4(uint32_t* r, uint32_t a) {
    asm volatile("ldmatrix.sync.aligned.m8n8.x4.shared.b16 {%0,%1,%2,%3}, [%4];"
                 : "=r"(r[0]), "=r"(r[1]), "=r"(r[2]), "=r"(r[3]) : "r"(a));
}
__device__ __forceinline__ void ldsm4t(uint32_t* r, uint32_t a) {
    asm volatile("ldmatrix.sync.aligned.m8n8.x4.trans.shared.b16 {%0,%1,%2,%3}, [%4];"
                 : "=r"(r[0]), "=r"(r[1]), "=r"(r[2]), "=r"(r[3]) : "r"(a));
}
__device__ __forceinline__ void mma16816(float* c, const uint32_t* a, const uint32_t* b) {
    asm volatile(
        "mma.sync.aligned.m16n8k16.row.col.f32.bf16.bf16.f32 "
        "{%0,%1,%2,%3}, {%4,%5,%6,%7}, {%8,%9}, {%0,%1,%2,%3};"
        : "+f"(c[0]), "+f"(c[1]), "+f"(c[2]), "+f"(c[3])
        : "r"(a[0]), "r"(a[1]), "r"(a[2]), "r"(a[3]), "r"(b[0]), "r"(b[1]));
}

// ---------------- stage 0: zero hist ----------------
__global__ void zeroK() {
    int i = blockIdx.x * blockDim.x + threadIdx.x;
    if (i < 65536) g_hist[i] = 0;
    if (i == 0) g_cnt = 0;
}

// ---------------- stage 1: score + key + histogram ----------------
__global__ void scoreK(const float* __restrict__ rois, const float* __restrict__ logits) {
    int i = blockIdx.x * blockDim.x + threadIdx.x;
    if (i >= N_ROIS) return;
    float y1 = fminf(fmaxf(rois[i * 4 + 0], 0.f), IMGSZ);
    float x1 = fminf(fmaxf(rois[i * 4 + 1], 0.f), IMGSZ);
    float y2 = fminf(fmaxf(rois[i * 4 + 2], 0.f), IMGSZ);
    float x2 = fminf(fmaxf(rois[i * 4 + 3], 0.f), IMGSZ);
    bool valid = ((y2 - y1) >= MIN_SIZE) && ((x2 - x1) >= MIN_SIZE);
    float l0 = logits[i * 2 + 0], l1 = logits[i * 2 + 1];
    float m = fmaxf(l0, l1);
    float e0 = expf(l0 - m), e1 = expf(l1 - m);
    float score = valid ? (e1 / (e0 + e1)) : -1.0f;
    unsigned b = __float_as_uint(score);
    unsigned key = (b & 0x80000000u) ? ~b : (b | 0x80000000u);
    g_keys[i] = ((unsigned long long)key << 32) | (unsigned)(~(unsigned)i);
    atomicAdd(&g_hist[key >> 16], 1);
}

// ---------------- stage 2: threshold bin ----------------
__global__ void threshK() {
    __shared__ int suf[1024];
    int t = threadIdx.x;
    int s = 0;
    for (int b = t * 64; b < t * 64 + 64; b++) s += g_hist[b];
    suf[t] = s;
    __syncthreads();
    for (int off = 1; off < 1024; off <<= 1) {
        int v = (t + off < 1024) ? suf[t + off] : 0;
        __syncthreads();
        suf[t] += v;
        __syncthreads();
    }
    int run = (t + 1 < 1024) ? suf[t + 1] : 0;
    for (int b = t * 64 + 63; b >= t * 64; b--) {
        int h = g_hist[b];
        int ge = run + h;
        if (ge >= PRE_NMS && run < PRE_NMS) g_threshBin = b;
        run = ge;
    }
}

// ---------------- stage 3: compact ----------------
__global__ void compactK() {
    int i = blockIdx.x * blockDim.x + threadIdx.x;
    if (i >= N_ROIS) return;
    unsigned long long k = g_keys[i];
    int bin = (int)(k >> 48);
    if (bin >= g_threshBin) {
        int pos = atomicAdd(&g_cnt, 1);
        if (pos < SORT_N) g_cand[pos] = k;
    }
}

// ---------------- stage 4: bitonic sort + emit boxes ----------------
__global__ void sortK(const float* __restrict__ rois) {
    __shared__ unsigned long long s[SORT_N];
    int tid = threadIdx.x;
    int cnt = g_cnt; if (cnt > SORT_N) cnt = SORT_N;
    for (int i = tid; i < SORT_N; i += 1024) s[i] = (i < cnt) ? g_cand[i] : 0ULL;
    __syncthreads();
    for (int k = 2; k <= SORT_N; k <<= 1) {
        for (int j = k >> 1; j > 0; j >>= 1) {
            for (int i = tid; i < SORT_N; i += 1024) {
                int l = i ^ j;
                if (l > i) {
                    unsigned long long a = s[i], b = s[l];
                    bool desc = ((i & k) == 0);
                    bool sw = desc ? (a < b) : (a > b);
                    if (sw) { s[i] = b; s[l] = a; }
                }
            }
            __syncthreads();
        }
    }
    for (int r = tid; r < PRE_NMS; r += 1024) {
        int idx = (int)(~(unsigned)s[r]);
        g_boxes[r * 4 + 0] = fminf(fmaxf(rois[idx * 4 + 0], 0.f), IMGSZ);
        g_boxes[r * 4 + 1] = fminf(fmaxf(rois[idx * 4 + 1], 0.f), IMGSZ);
        g_boxes[r * 4 + 2] = fminf(fmaxf(rois[idx * 4 + 2], 0.f), IMGSZ);
        g_boxes[r * 4 + 3] = fminf(fmaxf(rois[idx * 4 + 3], 0.f), IMGSZ);
    }
}

// ---------------- stage 5: NMS IoU bitmask ----------------
__global__ void nmsMaskK() {
    __shared__ float col[64][4];
    int t = threadIdx.x;
    int cbase = blockIdx.x * 64;
    if (cbase + t < PRE_NMS) {
        col[t][0] = g_boxes[(cbase + t) * 4 + 0];
        col[t][1] = g_boxes[(cbase + t) * 4 + 1];
        col[t][2] = g_boxes[(cbase + t) * 4 + 2];
        col[t][3] = g_boxes[(cbase + t) * 4 + 3];
    } else {
        col[t][0] = col[t][1] = col[t][2] = col[t][3] = 0.f;
    }
    __syncthreads();
    int row = blockIdx.y * 64 + t;
    if (row >= PRE_NMS) return;
    float ry1 = g_boxes[row * 4 + 0], rx1 = g_boxes[row * 4 + 1];
    float ry2 = g_boxes[row * 4 + 2], rx2 = g_boxes[row * 4 + 3];
    float ra = (ry2 - ry1) * (rx2 - rx1);
    unsigned long long bits = 0;
    #pragma unroll 8
    for (int j = 0; j < 64; j++) {
        int c = cbase + j;
        if (c >= PRE_NMS || c == row) continue;
        float ca = (col[j][2] - col[j][0]) * (col[j][3] - col[j][1]);
        float yy1 = fmaxf(ry1, col[j][0]);
        float xx1 = fmaxf(rx1, col[j][1]);
        float yy2 = fminf(ry2, col[j][2]);
        float xx2 = fminf(rx2, col[j][3]);
        float inter = fmaxf(yy2 - yy1, 0.f) * fmaxf(xx2 - xx1, 0.f);
        float iou = inter / (ra + ca - inter + 1e-9f);
        if (iou > IOU_TH) bits |= (1ull << j);
    }
    g_mask[row * 32 + blockIdx.x] = bits;
}

// ---------------- stage 6: sequential NMS scan ----------------
__global__ void nmsScanK(float* __restrict__ out) {
    int lane = threadIdx.x;
    __shared__ unsigned char keptFlag[PRE_NMS];
    for (int i = lane; i < PRE_NMS; i += 32) keptFlag[i] = 0;
    __syncwarp();
    unsigned long long remv = 0;
    int cnt = 0;
    for (int i = 0; i < PRE_NMS; i++) {
        unsigned long long w = __shfl_sync(0xffffffffu, remv, i >> 6);
        if (!((w >> (i & 63)) & 1ull)) {
            remv |= g_mask[i * 32 + lane];
            if (cnt < POST_NMS && lane == 0) { g_keep[cnt] = i; keptFlag[i] = 1; }
            cnt++;
            if (cnt == POST_NMS) break;
        }
    }
    __syncwarp();
    if (lane == 0 && cnt < POST_NMS) {
        int extras[POST_NMS]; int ne = 0;
        for (int i = 0; i < PRE_NMS && ne < POST_NMS - cnt; i++)
            if (!keptFlag[i]) extras[ne++] = i;
        int merged[POST_NMS]; int a = 0, b = 0;
        for (int o = 0; o < POST_NMS; o++) {
            int va = (a < cnt) ? g_keep[a] : 0x7fffffff;
            int vb = (b < ne) ? extras[b] : 0x7fffffff;
            if (va < vb) { merged[o] = va; a++; } else { merged[o] = vb; b++; }
        }
        for (int o = 0; o < POST_NMS; o++) g_keep[o] = merged[o];
    }
    __syncwarp();
    for (int r = lane; r < POST_NMS; r += 32) {
        int idx = g_keep[r];
        #pragma unroll
        for (int j = 0; j < 4; j++) {
            float v = g_boxes[idx * 4 + j];
            g_roisKept[r * 4 + j] = v;
            out[OFF_ROIS + r * 4 + j] = v;
        }
    }
}

// ---------------- stage 7: transpose CHW -> HWC ----------------
__global__ void transposeK(const float* __restrict__ feat) {
    __shared__ float tile[32][33];
    int p = blockIdx.x * 32 + threadIdx.x;
    int c = blockIdx.y * 32 + threadIdx.y;
    #pragma unroll
    for (int j = 0; j < 32; j += 8)
        if (p < 2500 && (c + j) < FEAT_C)
            tile[threadIdx.y + j][threadIdx.x] = feat[(c + j) * 2500 + p];
    __syncthreads();
    int c2 = blockIdx.y * 32 + threadIdx.x;
    int p2 = blockIdx.x * 32 + threadIdx.y;
    #pragma unroll
    for (int j = 0; j < 32; j += 8)
        if (c2 < FEAT_C && (p2 + j) < 2500)
            g_featT[(p2 + j) * FEAT_C + c2] = tile[threadIdx.x][threadIdx.y + j];
}

// ---------------- stage 8: ROI align ----------------
__global__ void roiAlignK() {
    int r = blockIdx.x;
    __shared__ float box[4];
    __shared__ int sy0[14], sy1[14], sx0[14], sx1[14];
    __shared__ float sly[14], slx[14];
    int t = threadIdx.x;
    if (t < 4) box[t] = g_roisKept[r * 4 + t] * (1.0f / 16.0f);
    __syncthreads();
    if (t < 28) {
        int d = t / 14, g = t % 14;
        float c1 = d ? box[1] : box[0];
        float c2 = d ? box[3] : box[2];
        float bsz = fmaxf(c2 - c1, 1.0f) * (1.0f / 7.0f);
        float gg = ((float)g + 0.5f) * 0.5f;
        float s = c1 + gg * bsz;
        s = fminf(fmaxf(s, 0.0f), 49.0f);
        float s0 = floorf(s);
        int i0 = (int)s0;
        int i1 = min(i0 + 1, 49);
        float l = s - s0;
        if (d == 0) { sy0[g] = i0; sy1[g] = i1; sly[g] = l; }
        else        { sx0[g] = i0; sx1[g] = i1; slx[g] = l; }
    }
    __syncthreads();
    float* outr = g_pooled + r * D_IN;
    for (int c = t; c < FEAT_C; c += 256) {
        #pragma unroll
        for (int oy = 0; oy < 7; oy++) {
            #pragma unroll
            for (int ox = 0; ox < 7; ox++) {
                float acc = 0.f;
                #pragma unroll
                for (int sy = 0; sy < 2; sy++) {
                    #pragma unroll
                    for (int sx = 0; sx < 2; sx++) {
                        int i = oy * 2 + sy, j = ox * 2 + sx;
                        int y0 = sy0[i], y1 = sy1[i], x0 = sx0[j], x1 = sx1[j];
                        float ly = sly[i], lx = slx[j];
                        const float* f = g_featT;
                        float v00 = f[(y0 * 50 + x0) * FEAT_C + c];
                        float v01 = f[(y0 * 50 + x1) * FEAT_C + c];
                        float v10 = f[(y1 * 50 + x0) * FEAT_C + c];
                        float v11 = f[(y1 * 50 + x1) * FEAT_C + c];
                        acc += (1.f - ly) * ((1.f - lx) * v00 + lx * v01)
                             + ly * ((1.f - lx) * v10 + lx * v11);
                    }
                }
                outr[(oy * 7 + ox) * FEAT_C + c] = acc * 0.25f;
            }
        }
    }
}

// ---------------- split fp32 -> bf16 hi/lo ----------------
__global__ void splitK_(const float* __restrict__ src, __nv_bfloat16* __restrict__ hi,
                        __nv_bfloat16* __restrict__ lo, int n) {
    int i = blockIdx.x * blockDim.x + threadIdx.x;
    if (i >= n) return;
    float v = src[i];
    __nv_bfloat16 h = __float2bfloat16(v);
    hi[i] = h;
    lo[i] = __float2bfloat16(v - __bfloat162float(h));
}

// ================= HMMA FC kernel =================
// part[ksp][128][4096] = A[128,K](bf16 hi/lo) @ B[K,4096](fp32, split on the fly)
// CTA: 256 thr (8 warps, 2M x 4N), tile M=128 N=128, K-chunk 32, double buffered.
// smem buffer (32KB): A rows 128 x 128B (hi k0..31 bytes 0-63 | lo bytes 64-127), SW128
//                     Bh at +16384 (two 64n halves of 128B rows), Bl at +24576.
#define FC_KC      32
#define FC_BUF     32768
#define FC_BH_OFF  16384
#define FC_BL_OFF  24576
#define SWZ(o) ((o) ^ (((o) >> 3) & 0x70))

template <int PERM>
__global__ __launch_bounds__(256, 2) void fcHmmaK(
    const __nv_bfloat16* __restrict__ Ah, const __nv_bfloat16* __restrict__ Al,
    const float* __restrict__ B, float* __restrict__ part,
    int K, int chunksPerCta)
{
    extern __shared__ char smem[];
    uint32_t sb = smem_u32(smem);
    int tid = threadIdx.x, wid = tid >> 5, lane = tid & 31;
    int mw = wid & 1, nw = wid >> 1;
    int n0 = blockIdx.x * 128;
    int ksp = blockIdx.y;
    int kbase = ksp * chunksPerCta * FC_KC;   // element offset of this k-slice

    float acc[4][4][4] = {};

    // per-thread ldmatrix address components
    int mat = lane >> 3, r8 = lane & 7;
    // A: row within warp tile, fixed per thread
    int rowA = mw * 64 + (mat & 1) * 8 + r8;
    uint32_t aRowOff = (uint32_t)rowA * 128;
    uint32_t aXor = (uint32_t)(rowA & 7) << 4;
    uint32_t aKb = (uint32_t)(mat >> 1) * 16;
    // B: k-row within kstep, n-group
    int krow = (mat & 1) * 8 + r8;
    uint32_t bXorBase = (uint32_t)r8 << 4;

    // staging
    auto stage = [&](int ci, uint32_t base) {
        int k0 = kbase + ci * FC_KC;
        // A: 128 rows x (4 hi segs + 4 lo segs) x 16B
        #pragma unroll
        for (int e = 0; e < 4; e++) {
            int flat = tid + e * 256;
            int seg = flat & 3, pr = (flat >> 2) & 1, row = flat >> 3;
            const __nv_bfloat16* src = (pr ? Al : Ah) + (size_t)row * K + k0 + seg * 8;
            uint4 v = *(const uint4*)src;
            sts128(base + SWZ((uint32_t)row * 128 + pr * 64 + seg * 16), v);
        }
        // B: 32 k-rows x 128 n fp32 -> bf16 hi/lo halves
        #pragma unroll
        for (int e = 0; e < 4; e++) {
            int flat = tid + e * 256;
            int n4 = flat & 31, k = flat >> 5;
            int gk = k0 + k;
            int grow = PERM ? ((gk & 511) * 49 + (gk >> 9)) : gk;
            float4 f = *(const float4*)(B + (size_t)grow * D_H + n0 + n4 * 4);
            uint32_t h0 = bfpack(f.x, f.y);
            uint32_t h1 = bfpack(f.z, f.w);
            float r0 = f.x - __uint_as_float(h0 << 16);
            float r1 = f.y - __uint_as_float(h0 & 0xffff0000u);
            float r2 = f.z - __uint_as_float(h1 << 16);
            float r3 = f.w - __uint_as_float(h1 & 0xffff0000u);
            uint32_t l0 = bfpack(r0, r1);
            uint32_t l1 = bfpack(r2, r3);
            uint32_t off = (uint32_t)(n4 >> 4) * 4096 + SWZ((uint32_t)k * 128 + (n4 & 15) * 8);
            sts64(base + FC_BH_OFF + off, h0, h1);
            sts64(base + FC_BL_OFF + off, l0, l1);
        }
    };

    stage(0, sb);
    __syncthreads();

    for (int c = 0; c < chunksPerCta; c++) {
        uint32_t buf = sb + (uint32_t)(c & 1) * FC_BUF;
        if (c + 1 < chunksPerCta) stage(c + 1, sb + (uint32_t)((c + 1) & 1) * FC_BUF);

        #pragma unroll
        for (int ks = 0; ks < 2; ks++) {
            // B addresses for this kstep
            uint32_t bRow = (uint32_t)(ks * 16 + krow) * 128;
            uint32_t ah[4][4], al[4][4], bh[2][4], bl[2][4];
            // A hi frags (term offset 0) and lo frags (offset 64)
            #pragma unroll
            for (int ti = 0; ti < 4; ti++) {
                uint32_t a0 = buf + aRowOff + (uint32_t)ti * 2048;
                ldsm4(ah[ti], a0 + (((uint32_t)(ks * 32) + aKb) ^ aXor));
                ldsm4(al[ti], a0 + (((uint32_t)(64 + ks * 32) + aKb) ^ aXor));
            }
            // B frags: group G covers n-tiles 2G, 2G+1
            #pragma unroll
            for (int G = 0; G < 2; G++) {
                int ngg = nw * 4 + G * 2 + (mat >> 1);
                uint32_t off = (uint32_t)(ngg >> 3) * 4096 + bRow
                             + (((uint32_t)(ngg & 7) * 16) ^ bXorBase);
                ldsm4t(bh[G], buf + FC_BH_OFF + off);
                ldsm4t(bl[G], buf + FC_BL_OFF + off);
            }
            // 3 terms: AhBh, AhBl, AlBh
            #pragma unroll
            for (int ti = 0; ti < 4; ti++)
                #pragma unroll
                for (int tj = 0; tj < 4; tj++) {
                    const uint32_t* bhp = &bh[tj >> 1][(tj & 1) * 2];
                    const uint32_t* blp = &bl[tj >> 1][(tj & 1) * 2];
                    mma16816(acc[ti][tj], ah[ti], bhp);
                    mma16816(acc[ti][tj], ah[ti], blp);
                    mma16816(acc[ti][tj], al[ti], bhp);
                }
        }
        __syncthreads();
    }

    // epilogue: write split-K partials
    int g = lane >> 2, t4 = lane & 3;
    float* pbase = part + ((size_t)ksp * 128) * D_H + n0;
    #pragma unroll
    for (int ti = 0; ti < 4; ti++) {
        int m = mw * 64 + ti * 16 + g;
        #pragma unroll
        for (int tj = 0; tj < 4; tj++) {
            int n = nw * 32 + tj * 8 + t4 * 2;
            float2 v0 = make_float2(acc[ti][tj][0], acc[ti][tj][1]);
            float2 v1 = make_float2(acc[ti][tj][2], acc[ti][tj][3]);
            *(float2*)(pbase + (size_t)m * D_H + n) = v0;
            *(float2*)(pbase + (size_t)(m + 8) * D_H + n) = v1;
        }
    }
}

// ---------------- reduce partials ----------------
__global__ void reduce1K(const float* __restrict__ part, const float* __restrict__ bias,
                         __nv_bfloat16* __restrict__ oh, __nv_bfloat16* __restrict__ ol) {
    int idx = blockIdx.x * blockDim.x + threadIdx.x;
    if (idx >= POST_NMS * D_H) return;
    int n = idx & (D_H - 1);
    float s = bias[n];
    #pragma unroll
    for (int p = 0; p < 8; p++) s += part[p * (POST_NMS * D_H) + idx];
    __nv_bfloat16 h = __float2bfloat16(s);
    oh[idx] = h;
    ol[idx] = __float2bfloat16(s - __bfloat162float(h));
}

__global__ void reduce2K(const float* __restrict__ part, const float* __restrict__ bias,
                         float* __restrict__ o) {
    int idx = blockIdx.x * blockDim.x + threadIdx.x;
    if (idx >= POST_NMS * D_H) return;
    int n = idx & (D_H - 1);
    float s = bias[n];
    #pragma unroll
    for (int p = 0; p < 4; p++) s += part[p * (POST_NMS * D_H) + idx];
    o[idx] = s;
}

// ---------------- heads: split-K SIMT GEMM ----------------
__global__ __launch_bounds__(256) void headK(
    const float* __restrict__ A, const float* __restrict__ W,
    float* __restrict__ part, int N, int kLen)
{
    __shared__ float As[16][68];
    __shared__ float Bs[16][68];
    int bn = blockIdx.x * 64, bm = blockIdx.y * 64;
    int k0base = blockIdx.z * kLen;
    int tid = threadIdx.x;
    int tx = tid & 15, ty = tid >> 4;
    float acc[4][4] = {};
    for (int k0 = 0; k0 < kLen; k0 += 16) {
        #pragma unroll
        for (int e = 0; e < 4; e++) {
            int flat = tid + e * 256;
            int m = flat >> 4, kk = flat & 15;
            As[kk][m] = A[(bm + m) * D_H + k0base + k0 + kk];
        }
        #pragma unroll
        for (int e = 0; e < 4; e++) {
            int flat = tid + e * 256;
            int kk = flat >> 6, n = flat & 63;
            int gn = bn + n;
            Bs[kk][n] = (gn < N) ? W[(size_t)(k0base + k0 + kk) * N + gn] : 0.0f;
        }
        __syncthreads();
        #pragma unroll
        for (int kk = 0; kk < 16; kk++) {
            float a[4], b[4];
            #pragma unroll
            for (int i = 0; i < 4; i++) a[i] = As[kk][ty * 4 + i];
            #pragma unroll
            for (int j = 0; j < 4; j++) b[j] = Bs[kk][tx * 4 + j];
            #pragma unroll
            for (int i = 0; i < 4; i++)
                #pragma unroll
                for (int j = 0; j < 4; j++)
                    acc[i][j] = fmaf(a[i], b[j], acc[i][j]);
        }
        __syncthreads();
    }
    #pragma unroll
    for (int i = 0; i < 4; i++) {
        int gm = bm + ty * 4 + i;
        #pragma unroll
        for (int j = 0; j < 4; j++) {
            int gn = bn + tx * 4 + j;
            if (gn < N) part[(size_t)blockIdx.z * 128 * N + gm * N + gn] = acc[i][j];
        }
    }
}

__global__ void headRedK(const float* __restrict__ part, const float* __restrict__ bias,
                         float* __restrict__ out, int N) {
    int idx = blockIdx.x * blockDim.x + threadIdx.x;
    if (idx >= 128 * N) return;
    int n = idx % N;
    float s = bias[n];
    #pragma unroll
    for (int p = 0; p < 8; p++) s += part[p * 128 * N + idx];
    out[idx] = s;
}

// ---------------- launcher ----------------
extern "C" void kernel_launch(void* const* d_in, const int* in_sizes, int n_in,
                              void* d_out, int out_size)
{
    const float* features = (const float*)d_in[0];
    const float* rois     = (const float*)d_in[1];
    const float* logits   = (const float*)d_in[2];
    const float* W1 = (const float*)d_in[3];
    const float* b1 = (const float*)d_in[4];
    const float* W2 = (const float*)d_in[5];
    const float* b2 = (const float*)d_in[6];
    const float* Wc = (const float*)d_in[7];
    const float* bc = (const float*)d_in[8];
    const float* Wd = (const float*)d_in[9];
    const float* bd = (const float*)d_in[10];
    float* out = (float*)d_out;

    float* pooled; cudaGetSymbolAddress((void**)&pooled, g_pooled);
    __nv_bfloat16* A1h; cudaGetSymbolAddress((void**)&A1h, g_A1h);
    __nv_bfloat16* A1l; cudaGetSymbolAddress((void**)&A1l, g_A1l);
    __nv_bfloat16* A2h; cudaGetSymbolAddress((void**)&A2h, g_A2h);
    __nv_bfloat16* A2l; cudaGetSymbolAddress((void**)&A2l, g_A2l);
    float* part; cudaGetSymbolAddress((void**)&part, g_part);
    float* h2;   cudaGetSymbolAddress((void**)&h2, g_h2);

    const int SMEM_BYTES = 2 * FC_BUF;  // 64 KB
    cudaFuncSetAttribute(fcHmmaK<1>, cudaFuncAttributeMaxDynamicSharedMemorySize, SMEM_BYTES);
    cudaFuncSetAttribute(fcHmmaK<0>, cudaFuncAttributeMaxDynamicSharedMemorySize, SMEM_BYTES);

    zeroK<<<64, 1024>>>();
    scoreK<<<(N_ROIS + 255) / 256, 256>>>(rois, logits);
    threshK<<<1, 1024>>>();
    compactK<<<(N_ROIS + 255) / 256, 256>>>();
    sortK<<<1, 1024>>>(rois);
    nmsMaskK<<<dim3(32, 32), 64>>>();
    nmsScanK<<<1, 32>>>(out);
    transposeK<<<dim3(79, 16), dim3(32, 8)>>>(features);
    roiAlignK<<<POST_NMS, 256>>>();

    splitK_<<<(POST_NMS * D_IN + 255) / 256, 256>>>(pooled, A1h, A1l, POST_NMS * D_IN);

    // FC1: K=25088 = 8 ksplits * 98 chunks * 32
    fcHmmaK<1><<<dim3(32, 8), 256, SMEM_BYTES>>>(A1h, A1l, W1, part, D_IN, 98);
    reduce1K<<<(POST_NMS * D_H + 255) / 256, 256>>>(part, b1, A2h, A2l);

    // FC2: K=4096 = 4 ksplits * 32 chunks * 32
    fcHmmaK<0><<<dim3(32, 4), 256, SMEM_BYTES>>>(A2h, A2l, W2, part, D_H, 32);
    reduce2K<<<(POST_NMS * D_H + 255) / 256, 256>>>(part, b2, h2);

    // heads: split-K 8 x 512
    headK<<<dim3(1, 2, 8), 256>>>(h2, Wc, part, NC, 512);
    headRedK<<<(128 * NC + 255) / 256, 256>>>(part, bc, out, NC);
    headK<<<dim3(2, 2, 8), 256>>>(h2, Wd, part + (1 << 21), NC * 4, 512);
    headRedK<<<(128 * NC * 4 + 255) / 256, 256>>>(part + (1 << 21), bd, out + OFF_DELTAS, NC * 4);
}

// round 5
// speedup vs baseline: 5.0557x; 1.0074x over previous
#include <cuda_runtime.h>
#include <cuda_bf16.h>
#include <math.h>
#include <stdint.h>

// ---------------- constants ----------------
#define N_ROIS   22500
#define IMGSZ    800.0f
#define MIN_SIZE 16.0f
#define PRE_NMS  2000
#define POST_NMS 128
#define IOU_TH   0.7f
#define FEAT_C   512
#define FEAT_HW  50
#define D_IN     25088   // 512*7*7
#define D_H      4096
#define NC       21
#define SORT_N   4096

#define OFF_DELTAS 2688
#define OFF_ROIS   13440

// ---------------- device scratch ----------------
__device__ float              g_featT[FEAT_HW * FEAT_HW * FEAT_C];
__device__ __align__(16) __nv_bfloat16 g_A1h[POST_NMS * D_IN];
__device__ __align__(16) __nv_bfloat16 g_A1l[POST_NMS * D_IN];
__device__ __align__(16) __nv_bfloat16 g_A2h[POST_NMS * D_H];
__device__ __align__(16) __nv_bfloat16 g_A2l[POST_NMS * D_H];
__device__ float              g_part[8 * POST_NMS * D_H];   // split-K partials (16MB)
__device__ float              g_h2[POST_NMS * D_H];
__device__ unsigned long long g_keys[N_ROIS];
__device__ int                g_hist[65536];
__device__ int                g_cnt;
__device__ int                g_threshBin;
__device__ unsigned long long g_cand[SORT_N];
__device__ float              g_boxes[PRE_NMS * 4];
__device__ unsigned long long g_mask[PRE_NMS * 32];
__device__ int                g_keep[POST_NMS];
__device__ float              g_roisKept[POST_NMS * 4];

// ================= helpers =================
__device__ __forceinline__ uint32_t smem_u32(const void* p) {
    uint32_t a;
    asm("{ .reg .u64 t; cvta.to.shared.u64 t, %1; cvt.u32.u64 %0, t; }" : "=r"(a) : "l"(p));
    return a;
}
__device__ __forceinline__ void sts64(uint32_t a, uint32_t w0, uint32_t w1) {
    asm volatile("st.shared.v2.b32 [%0], {%1,%2};" :: "r"(a), "r"(w0), "r"(w1) : "memory");
}
__device__ __forceinline__ void cpasync16(uint32_t saddr, const void* g) {
    asm volatile("cp.async.cg.shared.global [%0], [%1], 16;" :: "r"(saddr), "l"(g) : "memory");
}
__device__ __forceinline__ void cp_commit() {
    asm volatile("cp.async.commit_group;" ::: "memory");
}
__device__ __forceinline__ void cp_wait0() {
    asm volatile("cp.async.wait_group 0;" ::: "memory");
}
__device__ __forceinline__ uint32_t bfpack(float lo, float hi) {
    uint32_t r;
    asm("cvt.rn.bf16x2.f32 %0, %1, %2;" : "=r"(r) : "f"(hi), "f"(lo));
    return r;
}
__device__ __forceinline__ void ldsm4(uint32_t* r, uint32_t a) {
    asm volatile("ldmatrix.sync.aligned.m8n8.x4.shared.b16 {%0,%1,%2,%3}, [%4];"
                 : "=r"(r[0]), "=r"(r[1]), "=r"(r[2]), "=r"(r[3]) : "r"(a));
}
__device__ __forceinline__ void ldsm4t(uint32_t* r, uint32_t a) {
    asm volatile("ldmatrix.sync.aligned.m8n8.x4.trans.shared.b16 {%0,%1,%2,%3}, [%4];"
                 : "=r"(r[0]), "=r"(r[1]), "=r"(r[2]), "=r"(r[3]) : "r"(a));
}
__device__ __forceinline__ void mma16816(float* c, const uint32_t* a, const uint32_t* b) {
    asm volatile(
        "mma.sync.aligned.m16n8k16.row.col.f32.bf16.bf16.f32 "
        "{%0,%1,%2,%3}, {%4,%5,%6,%7}, {%8,%9}, {%0,%1,%2,%3};"
        : "+f"(c[0]), "+f"(c[1]), "+f"(c[2]), "+f"(c[3])
        : "r"(a[0]), "r"(a[1]), "r"(a[2]), "r"(a[3]), "r"(b[0]), "r"(b[1]));
}

// ---------------- stage 0: zero hist ----------------
__global__ void zeroK() {
    int i = blockIdx.x * blockDim.x + threadIdx.x;
    if (i < 65536) g_hist[i] = 0;
    if (i == 0) g_cnt = 0;
}

// ---------------- stage 1: score + key + histogram ----------------
__global__ void scoreK(const float* __restrict__ rois, const float* __restrict__ logits) {
    int i = blockIdx.x * blockDim.x + threadIdx.x;
    if (i >= N_ROIS) return;
    float y1 = fminf(fmaxf(rois[i * 4 + 0], 0.f), IMGSZ);
    float x1 = fminf(fmaxf(rois[i * 4 + 1], 0.f), IMGSZ);
    float y2 = fminf(fmaxf(rois[i * 4 + 2], 0.f), IMGSZ);
    float x2 = fminf(fmaxf(rois[i * 4 + 3], 0.f), IMGSZ);
    bool valid = ((y2 - y1) >= MIN_SIZE) && ((x2 - x1) >= MIN_SIZE);
    float l0 = logits[i * 2 + 0], l1 = logits[i * 2 + 1];
    float m = fmaxf(l0, l1);
    float e0 = expf(l0 - m), e1 = expf(l1 - m);
    float score = valid ? (e1 / (e0 + e1)) : -1.0f;
    unsigned b = __float_as_uint(score);
    unsigned key = (b & 0x80000000u) ? ~b : (b | 0x80000000u);
    g_keys[i] = ((unsigned long long)key << 32) | (unsigned)(~(unsigned)i);
    atomicAdd(&g_hist[key >> 16], 1);
}

// ---------------- stage 2: threshold bin ----------------
__global__ void threshK() {
    __shared__ int suf[1024];
    int t = threadIdx.x;
    int s = 0;
    for (int b = t * 64; b < t * 64 + 64; b++) s += g_hist[b];
    suf[t] = s;
    __syncthreads();
    for (int off = 1; off < 1024; off <<= 1) {
        int v = (t + off < 1024) ? suf[t + off] : 0;
        __syncthreads();
        suf[t] += v;
        __syncthreads();
    }
    int run = (t + 1 < 1024) ? suf[t + 1] : 0;
    for (int b = t * 64 + 63; b >= t * 64; b--) {
        int h = g_hist[b];
        int ge = run + h;
        if (ge >= PRE_NMS && run < PRE_NMS) g_threshBin = b;
        run = ge;
    }
}

// ---------------- stage 3: compact ----------------
__global__ void compactK() {
    int i = blockIdx.x * blockDim.x + threadIdx.x;
    if (i >= N_ROIS) return;
    unsigned long long k = g_keys[i];
    int bin = (int)(k >> 48);
    if (bin >= g_threshBin) {
        int pos = atomicAdd(&g_cnt, 1);
        if (pos < SORT_N) g_cand[pos] = k;
    }
}

// ---------------- stage 4: bitonic sort + emit boxes ----------------
__global__ void sortK(const float* __restrict__ rois) {
    __shared__ unsigned long long s[SORT_N];
    int tid = threadIdx.x;
    int cnt = g_cnt; if (cnt > SORT_N) cnt = SORT_N;
    for (int i = tid; i < SORT_N; i += 1024) s[i] = (i < cnt) ? g_cand[i] : 0ULL;
    __syncthreads();
    for (int k = 2; k <= SORT_N; k <<= 1) {
        for (int j = k >> 1; j > 0; j >>= 1) {
            for (int i = tid; i < SORT_N; i += 1024) {
                int l = i ^ j;
                if (l > i) {
                    unsigned long long a = s[i], b = s[l];
                    bool desc = ((i & k) == 0);
                    bool sw = desc ? (a < b) : (a > b);
                    if (sw) { s[i] = b; s[l] = a; }
                }
            }
            __syncthreads();
        }
    }
    for (int r = tid; r < PRE_NMS; r += 1024) {
        int idx = (int)(~(unsigned)s[r]);
        g_boxes[r * 4 + 0] = fminf(fmaxf(rois[idx * 4 + 0], 0.f), IMGSZ);
        g_boxes[r * 4 + 1] = fminf(fmaxf(rois[idx * 4 + 1], 0.f), IMGSZ);
        g_boxes[r * 4 + 2] = fminf(fmaxf(rois[idx * 4 + 2], 0.f), IMGSZ);
        g_boxes[r * 4 + 3] = fminf(fmaxf(rois[idx * 4 + 3], 0.f), IMGSZ);
    }
}

// ---------------- stage 5: NMS IoU bitmask ----------------
__global__ void nmsMaskK() {
    __shared__ float col[64][4];
    int t = threadIdx.x;
    int cbase = blockIdx.x * 64;
    if (cbase + t < PRE_NMS) {
        col[t][0] = g_boxes[(cbase + t) * 4 + 0];
        col[t][1] = g_boxes[(cbase + t) * 4 + 1];
        col[t][2] = g_boxes[(cbase + t) * 4 + 2];
        col[t][3] = g_boxes[(cbase + t) * 4 + 3];
    } else {
        col[t][0] = col[t][1] = col[t][2] = col[t][3] = 0.f;
    }
    __syncthreads();
    int row = blockIdx.y * 64 + t;
    if (row >= PRE_NMS) return;
    float ry1 = g_boxes[row * 4 + 0], rx1 = g_boxes[row * 4 + 1];
    float ry2 = g_boxes[row * 4 + 2], rx2 = g_boxes[row * 4 + 3];
    float ra = (ry2 - ry1) * (rx2 - rx1);
    unsigned long long bits = 0;
    #pragma unroll 8
    for (int j = 0; j < 64; j++) {
        int c = cbase + j;
        if (c >= PRE_NMS || c == row) continue;
        float ca = (col[j][2] - col[j][0]) * (col[j][3] - col[j][1]);
        float yy1 = fmaxf(ry1, col[j][0]);
        float xx1 = fmaxf(rx1, col[j][1]);
        float yy2 = fminf(ry2, col[j][2]);
        float xx2 = fminf(rx2, col[j][3]);
        float inter = fmaxf(yy2 - yy1, 0.f) * fmaxf(xx2 - xx1, 0.f);
        float iou = inter / (ra + ca - inter + 1e-9f);
        if (iou > IOU_TH) bits |= (1ull << j);
    }
    g_mask[row * 32 + blockIdx.x] = bits;
}

// ---------------- stage 6: sequential NMS scan ----------------
__global__ void nmsScanK(float* __restrict__ out) {
    int lane = threadIdx.x;
    __shared__ unsigned char keptFlag[PRE_NMS];
    for (int i = lane; i < PRE_NMS; i += 32) keptFlag[i] = 0;
    __syncwarp();
    unsigned long long remv = 0;
    int cnt = 0;
    for (int i = 0; i < PRE_NMS; i++) {
        unsigned long long w = __shfl_sync(0xffffffffu, remv, i >> 6);
        if (!((w >> (i & 63)) & 1ull)) {
            remv |= g_mask[i * 32 + lane];
            if (cnt < POST_NMS && lane == 0) { g_keep[cnt] = i; keptFlag[i] = 1; }
            cnt++;
            if (cnt == POST_NMS) break;
        }
    }
    __syncwarp();
    if (lane == 0 && cnt < POST_NMS) {
        int extras[POST_NMS]; int ne = 0;
        for (int i = 0; i < PRE_NMS && ne < POST_NMS - cnt; i++)
            if (!keptFlag[i]) extras[ne++] = i;
        int merged[POST_NMS]; int a = 0, b = 0;
        for (int o = 0; o < POST_NMS; o++) {
            int va = (a < cnt) ? g_keep[a] : 0x7fffffff;
            int vb = (b < ne) ? extras[b] : 0x7fffffff;
            if (va < vb) { merged[o] = va; a++; } else { merged[o] = vb; b++; }
        }
        for (int o = 0; o < POST_NMS; o++) g_keep[o] = merged[o];
    }
    __syncwarp();
    for (int r = lane; r < POST_NMS; r += 32) {
        int idx = g_keep[r];
        #pragma unroll
        for (int j = 0; j < 4; j++) {
            float v = g_boxes[idx * 4 + j];
            g_roisKept[r * 4 + j] = v;
            out[OFF_ROIS + r * 4 + j] = v;
        }
    }
}

// ---------------- stage 7: transpose CHW -> HWC ----------------
__global__ void transposeK(const float* __restrict__ feat) {
    __shared__ float tile[32][33];
    int p = blockIdx.x * 32 + threadIdx.x;
    int c = blockIdx.y * 32 + threadIdx.y;
    #pragma unroll
    for (int j = 0; j < 32; j += 8)
        if (p < 2500 && (c + j) < FEAT_C)
            tile[threadIdx.y + j][threadIdx.x] = feat[(c + j) * 2500 + p];
    __syncthreads();
    int c2 = blockIdx.y * 32 + threadIdx.x;
    int p2 = blockIdx.x * 32 + threadIdx.y;
    #pragma unroll
    for (int j = 0; j < 32; j += 8)
        if (c2 < FEAT_C && (p2 + j) < 2500)
            g_featT[(p2 + j) * FEAT_C + c2] = tile[threadIdx.x][threadIdx.y + j];
}

// ---------------- stage 8: ROI align (fused fp32->bf16 hi/lo split) ----------------
__global__ void roiAlignK() {
    int r = blockIdx.x;
    __shared__ float box[4];
    __shared__ int sy0[14], sy1[14], sx0[14], sx1[14];
    __shared__ float sly[14], slx[14];
    int t = threadIdx.x;
    if (t < 4) box[t] = g_roisKept[r * 4 + t] * (1.0f / 16.0f);
    __syncthreads();
    if (t < 28) {
        int d = t / 14, g = t % 14;
        float c1 = d ? box[1] : box[0];
        float c2 = d ? box[3] : box[2];
        float bsz = fmaxf(c2 - c1, 1.0f) * (1.0f / 7.0f);
        float gg = ((float)g + 0.5f) * 0.5f;
        float s = c1 + gg * bsz;
        s = fminf(fmaxf(s, 0.0f), 49.0f);
        float s0 = floorf(s);
        int i0 = (int)s0;
        int i1 = min(i0 + 1, 49);
        float l = s - s0;
        if (d == 0) { sy0[g] = i0; sy1[g] = i1; sly[g] = l; }
        else        { sx0[g] = i0; sx1[g] = i1; slx[g] = l; }
    }
    __syncthreads();
    __nv_bfloat16* outh = g_A1h + (size_t)r * D_IN;
    __nv_bfloat16* outl = g_A1l + (size_t)r * D_IN;
    for (int c = t; c < FEAT_C; c += 256) {
        #pragma unroll
        for (int oy = 0; oy < 7; oy++) {
            #pragma unroll
            for (int ox = 0; ox < 7; ox++) {
                float acc = 0.f;
                #pragma unroll
                for (int sy = 0; sy < 2; sy++) {
                    #pragma unroll
                    for (int sx = 0; sx < 2; sx++) {
                        int i = oy * 2 + sy, j = ox * 2 + sx;
                        int y0 = sy0[i], y1 = sy1[i], x0 = sx0[j], x1 = sx1[j];
                        float ly = sly[i], lx = slx[j];
                        const float* f = g_featT;
                        float v00 = f[(y0 * 50 + x0) * FEAT_C + c];
                        float v01 = f[(y0 * 50 + x1) * FEAT_C + c];
                        float v10 = f[(y1 * 50 + x0) * FEAT_C + c];
                        float v11 = f[(y1 * 50 + x1) * FEAT_C + c];
                        acc += (1.f - ly) * ((1.f - lx) * v00 + lx * v01)
                             + ly * ((1.f - lx) * v10 + lx * v11);
                    }
                }
                float v = acc * 0.25f;
                __nv_bfloat16 h = __float2bfloat16(v);
                int o = (oy * 7 + ox) * FEAT_C + c;
                outh[o] = h;
                outl[o] = __float2bfloat16(v - __bfloat162float(h));
            }
        }
    }
}

// ================= HMMA FC kernel =================
// part[ksp][128][4096] = A[128,K](bf16 hi/lo) @ B[K,4096](fp32, split on the fly)
// CTA: 256 thr (8 warps, 2M x 4N), tile M=128 N=128, K-chunk 32, double buffered.
// smem buffer (32KB): A rows 128 x 128B (hi k0..31 bytes 0-63 | lo bytes 64-127), SW128
//                     Bh at +16384 (two 64n halves of 128B rows), Bl at +24576.
#define FC_KC      32
#define FC_BUF     32768
#define FC_BH_OFF  16384
#define FC_BL_OFF  24576
#define SWZ(o) ((o) ^ (((o) >> 3) & 0x70))

template <int PERM>
__global__ __launch_bounds__(256, 2) void fcHmmaK(
    const __nv_bfloat16* __restrict__ Ah, const __nv_bfloat16* __restrict__ Al,
    const float* __restrict__ B, float* __restrict__ part,
    int K, int chunksPerCta)
{
    extern __shared__ char smem[];
    uint32_t sb = smem_u32(smem);
    int tid = threadIdx.x, wid = tid >> 5, lane = tid & 31;
    int mw = wid & 1, nw = wid >> 1;
    int n0 = blockIdx.x * 128;
    int ksp = blockIdx.y;
    int kbase = ksp * chunksPerCta * FC_KC;   // element offset of this k-slice

    float acc[4][4][4] = {};

    // per-thread ldmatrix address components
    int mat = lane >> 3, r8 = lane & 7;
    int rowA = mw * 64 + (mat & 1) * 8 + r8;
    uint32_t aRowOff = (uint32_t)rowA * 128;
    uint32_t aXor = (uint32_t)(rowA & 7) << 4;
    uint32_t aKb = (uint32_t)(mat >> 1) * 16;
    int krow = (mat & 1) * 8 + r8;
    uint32_t bXorBase = (uint32_t)r8 << 4;

    // staging: A via cp.async (no conversion), B via LDG->cvt->STS
    auto stage = [&](int ci, uint32_t base) {
        int k0 = kbase + ci * FC_KC;
        #pragma unroll
        for (int e = 0; e < 4; e++) {
            int flat = tid + e * 256;
            int seg = flat & 3, pr = (flat >> 2) & 1, row = flat >> 3;
            const __nv_bfloat16* src = (pr ? Al : Ah) + (size_t)row * K + k0 + seg * 8;
            cpasync16(base + SWZ((uint32_t)row * 128 + pr * 64 + seg * 16), src);
        }
        #pragma unroll
        for (int e = 0; e < 4; e++) {
            int flat = tid + e * 256;
            int n4 = flat & 31, k = flat >> 5;
            int gk = k0 + k;
            int grow = PERM ? ((gk & 511) * 49 + (gk >> 9)) : gk;
            float4 f = *(const float4*)(B + (size_t)grow * D_H + n0 + n4 * 4);
            uint32_t h0 = bfpack(f.x, f.y);
            uint32_t h1 = bfpack(f.z, f.w);
            float r0 = f.x - __uint_as_float(h0 << 16);
            float r1 = f.y - __uint_as_float(h0 & 0xffff0000u);
            float r2 = f.z - __uint_as_float(h1 << 16);
            float r3 = f.w - __uint_as_float(h1 & 0xffff0000u);
            uint32_t l0 = bfpack(r0, r1);
            uint32_t l1 = bfpack(r2, r3);
            uint32_t off = (uint32_t)(n4 >> 4) * 4096 + SWZ((uint32_t)k * 128 + (n4 & 15) * 8);
            sts64(base + FC_BH_OFF + off, h0, h1);
            sts64(base + FC_BL_OFF + off, l0, l1);
        }
        cp_commit();
    };

    stage(0, sb);
    cp_wait0();
    __syncthreads();

    for (int c = 0; c < chunksPerCta; c++) {
        uint32_t buf = sb + (uint32_t)(c & 1) * FC_BUF;
        if (c + 1 < chunksPerCta) stage(c + 1, sb + (uint32_t)((c + 1) & 1) * FC_BUF);

        // term-major ordering to minimize live registers:
        //   ah+bh -> AhBh ; bl -> AhBl ; al (ah dead) -> AlBh (bh reused)
        #pragma unroll
        for (int ks = 0; ks < 2; ks++) {
            uint32_t bRow = (uint32_t)(ks * 16 + krow) * 128;
            uint32_t ah[4][4];
            #pragma unroll
            for (int ti = 0; ti < 4; ti++)
                ldsm4(ah[ti], buf + aRowOff + (uint32_t)ti * 2048
                              + (((uint32_t)(ks * 32) + aKb) ^ aXor));
            uint32_t bh[2][4];
            #pragma unroll
            for (int G = 0; G < 2; G++) {
                int ngg = nw * 4 + G * 2 + (mat >> 1);
                uint32_t off = (uint32_t)(ngg >> 3) * 4096 + bRow
                             + (((uint32_t)(ngg & 7) * 16) ^ bXorBase);
                ldsm4t(bh[G], buf + FC_BH_OFF + off);
            }
            #pragma unroll
            for (int ti = 0; ti < 4; ti++)
                #pragma unroll
                for (int tj = 0; tj < 4; tj++)
                    mma16816(acc[ti][tj], ah[ti], &bh[tj >> 1][(tj & 1) * 2]);

            uint32_t bl[2][4];
            #pragma unroll
            for (int G = 0; G < 2; G++) {
                int ngg = nw * 4 + G * 2 + (mat >> 1);
                uint32_t off = (uint32_t)(ngg >> 3) * 4096 + bRow
                             + (((uint32_t)(ngg & 7) * 16) ^ bXorBase);
                ldsm4t(bl[G], buf + FC_BL_OFF + off);
            }
            #pragma unroll
            for (int ti = 0; ti < 4; ti++)
                #pragma unroll
                for (int tj = 0; tj < 4; tj++)
                    mma16816(acc[ti][tj], ah[ti], &bl[tj >> 1][(tj & 1) * 2]);

            uint32_t al[4][4];
            #pragma unroll
            for (int ti = 0; ti < 4; ti++)
                ldsm4(al[ti], buf + aRowOff + (uint32_t)ti * 2048
                              + (((uint32_t)(64 + ks * 32) + aKb) ^ aXor));
            #pragma unroll
            for (int ti = 0; ti < 4; ti++)
                #pragma unroll
                for (int tj = 0; tj < 4; tj++)
                    mma16816(acc[ti][tj], al[ti], &bh[tj >> 1][(tj & 1) * 2]);
        }
        cp_wait0();
        __syncthreads();
    }

    // epilogue: write split-K partials
    int g = lane >> 2, t4 = lane & 3;
    float* pbase = part + ((size_t)ksp * 128) * D_H + n0;
    #pragma unroll
    for (int ti = 0; ti < 4; ti++) {
        int m = mw * 64 + ti * 16 + g;
        #pragma unroll
        for (int tj = 0; tj < 4; tj++) {
            int n = nw * 32 + tj * 8 + t4 * 2;
            float2 v0 = make_float2(acc[ti][tj][0], acc[ti][tj][1]);
            float2 v1 = make_float2(acc[ti][tj][2], acc[ti][tj][3]);
            *(float2*)(pbase + (size_t)m * D_H + n) = v0;
            *(float2*)(pbase + (size_t)(m + 8) * D_H + n) = v1;
        }
    }
}

// ---------------- reduce partials ----------------
__global__ void reduce1K(const float* __restrict__ part, const float* __restrict__ bias,
                         __nv_bfloat16* __restrict__ oh, __nv_bfloat16* __restrict__ ol) {
    int idx = blockIdx.x * blockDim.x + threadIdx.x;
    if (idx >= POST_NMS * D_H) return;
    int n = idx & (D_H - 1);
    float s = bias[n];
    #pragma unroll
    for (int p = 0; p < 8; p++) s += part[p * (POST_NMS * D_H) + idx];
    __nv_bfloat16 h = __float2bfloat16(s);
    oh[idx] = h;
    ol[idx] = __float2bfloat16(s - __bfloat162float(h));
}

__global__ void reduce2K(const float* __restrict__ part, const float* __restrict__ bias,
                         float* __restrict__ o) {
    int idx = blockIdx.x * blockDim.x + threadIdx.x;
    if (idx >= POST_NMS * D_H) return;
    int n = idx & (D_H - 1);
    float s = bias[n];
    #pragma unroll
    for (int p = 0; p < 8; p++) s += part[p * (POST_NMS * D_H) + idx];
    o[idx] = s;
}

// ---------------- heads: split-K SIMT GEMM ----------------
__global__ __launch_bounds__(256) void headK(
    const float* __restrict__ A, const float* __restrict__ W,
    float* __restrict__ part, int N, int kLen)
{
    __shared__ float As[16][68];
    __shared__ float Bs[16][68];
    int bn = blockIdx.x * 64, bm = blockIdx.y * 64;
    int k0base = blockIdx.z * kLen;
    int tid = threadIdx.x;
    int tx = tid & 15, ty = tid >> 4;
    float acc[4][4] = {};
    for (int k0 = 0; k0 < kLen; k0 += 16) {
        #pragma unroll
        for (int e = 0; e < 4; e++) {
            int flat = tid + e * 256;
            int m = flat >> 4, kk = flat & 15;
            As[kk][m] = A[(bm + m) * D_H + k0base + k0 + kk];
        }
        #pragma unroll
        for (int e = 0; e < 4; e++) {
            int flat = tid + e * 256;
            int kk = flat >> 6, n = flat & 63;
            int gn = bn + n;
            Bs[kk][n] = (gn < N) ? W[(size_t)(k0base + k0 + kk) * N + gn] : 0.0f;
        }
        __syncthreads();
        #pragma unroll
        for (int kk = 0; kk < 16; kk++) {
            float a[4], b[4];
            #pragma unroll
            for (int i = 0; i < 4; i++) a[i] = As[kk][ty * 4 + i];
            #pragma unroll
            for (int j = 0; j < 4; j++) b[j] = Bs[kk][tx * 4 + j];
            #pragma unroll
            for (int i = 0; i < 4; i++)
                #pragma unroll
                for (int j = 0; j < 4; j++)
                    acc[i][j] = fmaf(a[i], b[j], acc[i][j]);
        }
        __syncthreads();
    }
    #pragma unroll
    for (int i = 0; i < 4; i++) {
        int gm = bm + ty * 4 + i;
        #pragma unroll
        for (int j = 0; j < 4; j++) {
            int gn = bn + tx * 4 + j;
            if (gn < N) part[(size_t)blockIdx.z * 128 * N + gm * N + gn] = acc[i][j];
        }
    }
}

__global__ void headRedK(const float* __restrict__ part, const float* __restrict__ bias,
                         float* __restrict__ out, int N) {
    int idx = blockIdx.x * blockDim.x + threadIdx.x;
    if (idx >= 128 * N) return;
    int n = idx % N;
    float s = bias[n];
    #pragma unroll
    for (int p = 0; p < 8; p++) s += part[p * 128 * N + idx];
    out[idx] = s;
}

// ---------------- launcher ----------------
extern "C" void kernel_launch(void* const* d_in, const int* in_sizes, int n_in,
                              void* d_out, int out_size)
{
    const float* features = (const float*)d_in[0];
    const float* rois     = (const float*)d_in[1];
    const float* logits   = (const float*)d_in[2];
    const float* W1 = (const float*)d_in[3];
    const float* b1 = (const float*)d_in[4];
    const float* W2 = (const float*)d_in[5];
    const float* b2 = (const float*)d_in[6];
    const float* Wc = (const float*)d_in[7];
    const float* bc = (const float*)d_in[8];
    const float* Wd = (const float*)d_in[9];
    const float* bd = (const float*)d_in[10];
    float* out = (float*)d_out;

    __nv_bfloat16* A1h; cudaGetSymbolAddress((void**)&A1h, g_A1h);
    __nv_bfloat16* A1l; cudaGetSymbolAddress((void**)&A1l, g_A1l);
    __nv_bfloat16* A2h; cudaGetSymbolAddress((void**)&A2h, g_A2h);
    __nv_bfloat16* A2l; cudaGetSymbolAddress((void**)&A2l, g_A2l);
    float* part; cudaGetSymbolAddress((void**)&part, g_part);
    float* h2;   cudaGetSymbolAddress((void**)&h2, g_h2);

    const int SMEM_BYTES = 2 * FC_BUF;  // 64 KB
    cudaFuncSetAttribute(fcHmmaK<1>, cudaFuncAttributeMaxDynamicSharedMemorySize, SMEM_BYTES);
    cudaFuncSetAttribute(fcHmmaK<0>, cudaFuncAttributeMaxDynamicSharedMemorySize, SMEM_BYTES);

    zeroK<<<64, 1024>>>();
    scoreK<<<(N_ROIS + 255) / 256, 256>>>(rois, logits);
    threshK<<<1, 1024>>>();
    compactK<<<(N_ROIS + 255) / 256, 256>>>();
    sortK<<<1, 1024>>>(rois);
    nmsMaskK<<<dim3(32, 32), 64>>>();
    nmsScanK<<<1, 32>>>(out);
    transposeK<<<dim3(79, 16), dim3(32, 8)>>>(features);
    roiAlignK<<<POST_NMS, 256>>>();

    // FC1: K=25088 = 8 ksplits * 98 chunks * 32
    fcHmmaK<1><<<dim3(32, 8), 256, SMEM_BYTES>>>(A1h, A1l, W1, part, D_IN, 98);
    reduce1K<<<(POST_NMS * D_H + 255) / 256, 256>>>(part, b1, A2h, A2l);

    // FC2: K=4096 = 8 ksplits * 16 chunks * 32
    fcHmmaK<0><<<dim3(32, 8), 256, SMEM_BYTES>>>(A2h, A2l, W2, part, D_H, 16);
    reduce2K<<<(POST_NMS * D_H + 255) / 256, 256>>>(part, b2, h2);

    // heads: split-K 8 x 512
    headK<<<dim3(1, 2, 8), 256>>>(h2, Wc, part, NC, 512);
    headRedK<<<(128 * NC + 255) / 256, 256>>>(part, bc, out, NC);
    headK<<<dim3(2, 2, 8), 256>>>(h2, Wd, part + (1 << 21), NC * 4, 512);
    headRedK<<<(128 * NC * 4 + 255) / 256, 256>>>(part + (1 << 21), bd, out + OFF_DELTAS, NC * 4);
}

// round 6
// speedup vs baseline: 6.7848x; 1.3420x over previous
#include <cuda_runtime.h>
#include <cuda_fp16.h>
#include <math.h>
#include <stdint.h>

// ---------------- constants ----------------
#define N_ROIS   22500
#define IMGSZ    800.0f
#define MIN_SIZE 16.0f
#define PRE_NMS  2000
#define POST_NMS 128
#define IOU_TH   0.7f
#define FEAT_C   512
#define FEAT_HW  50
#define D_IN     25088   // 512*7*7
#define D_H      4096
#define NC       21
#define SORT_N   4096

#define OFF_DELTAS 2688
#define OFF_ROIS   13440

// ---------------- device scratch ----------------
__device__ float              g_featT[FEAT_HW * FEAT_HW * FEAT_C];
__device__ __align__(16) __half g_A1[POST_NMS * D_IN];   // pooled, fp16
__device__ __align__(16) __half g_A2[POST_NMS * D_H];    // h1, fp16
__device__ float              g_part[8 * POST_NMS * D_H];   // split-K partials (16MB)
__device__ float              g_h2[POST_NMS * D_H];
__device__ unsigned long long g_keys[N_ROIS];
__device__ int                g_hist[65536];
__device__ int                g_cnt;
__device__ int                g_threshBin;
__device__ unsigned long long g_cand[SORT_N];
__device__ float              g_boxes[PRE_NMS * 4];
__device__ unsigned long long g_mask[PRE_NMS * 32];
__device__ int                g_keep[POST_NMS];
__device__ float              g_roisKept[POST_NMS * 4];

// ================= helpers =================
__device__ __forceinline__ uint32_t smem_u32(const void* p) {
    uint32_t a;
    asm("{ .reg .u64 t; cvta.to.shared.u64 t, %1; cvt.u32.u64 %0, t; }" : "=r"(a) : "l"(p));
    return a;
}
__device__ __forceinline__ void sts64(uint32_t a, uint32_t w0, uint32_t w1) {
    asm volatile("st.shared.v2.b32 [%0], {%1,%2};" :: "r"(a), "r"(w0), "r"(w1) : "memory");
}
__device__ __forceinline__ void cpasync16(uint32_t saddr, const void* g) {
    asm volatile("cp.async.cg.shared.global [%0], [%1], 16;" :: "r"(saddr), "l"(g) : "memory");
}
__device__ __forceinline__ void cpasync8(uint32_t saddr, const void* g) {
    asm volatile("cp.async.ca.shared.global [%0], [%1], 8;" :: "r"(saddr), "l"(g) : "memory");
}
__device__ __forceinline__ void cp_commit() {
    asm volatile("cp.async.commit_group;" ::: "memory");
}
__device__ __forceinline__ void cp_wait0() {
    asm volatile("cp.async.wait_group 0;" ::: "memory");
}
__device__ __forceinline__ void cp_wait48() {
    asm volatile("cp.async.wait_group 48;" ::: "memory");
}
__device__ __forceinline__ uint32_t h2pack(float a, float b) {
    __half2 h = __floats2half2_rn(a, b);
    return *reinterpret_cast<uint32_t*>(&h);
}
__device__ __forceinline__ void ldsm4(uint32_t* r, uint32_t a) {
    asm volatile("ldmatrix.sync.aligned.m8n8.x4.shared.b16 {%0,%1,%2,%3}, [%4];"
                 : "=r"(r[0]), "=r"(r[1]), "=r"(r[2]), "=r"(r[3]) : "r"(a));
}
__device__ __forceinline__ void ldsm4t(uint32_t* r, uint32_t a) {
    asm volatile("ldmatrix.sync.aligned.m8n8.x4.trans.shared.b16 {%0,%1,%2,%3}, [%4];"
                 : "=r"(r[0]), "=r"(r[1]), "=r"(r[2]), "=r"(r[3]) : "r"(a));
}
__device__ __forceinline__ void mma16816(float* c, const uint32_t* a, const uint32_t* b) {
    asm volatile(
        "mma.sync.aligned.m16n8k16.row.col.f32.f16.f16.f32 "
        "{%0,%1,%2,%3}, {%4,%5,%6,%7}, {%8,%9}, {%0,%1,%2,%3};"
        : "+f"(c[0]), "+f"(c[1]), "+f"(c[2]), "+f"(c[3])
        : "r"(a[0]), "r"(a[1]), "r"(a[2]), "r"(a[3]), "r"(b[0]), "r"(b[1]));
}

// ---------------- stage 0: zero hist ----------------
__global__ void zeroK() {
    int i = blockIdx.x * blockDim.x + threadIdx.x;
    if (i < 65536) g_hist[i] = 0;
    if (i == 0) g_cnt = 0;
}

// ---------------- stage 1: score + key + histogram ----------------
__global__ void scoreK(const float* __restrict__ rois, const float* __restrict__ logits) {
    int i = blockIdx.x * blockDim.x + threadIdx.x;
    if (i >= N_ROIS) return;
    float y1 = fminf(fmaxf(rois[i * 4 + 0], 0.f), IMGSZ);
    float x1 = fminf(fmaxf(rois[i * 4 + 1], 0.f), IMGSZ);
    float y2 = fminf(fmaxf(rois[i * 4 + 2], 0.f), IMGSZ);
    float x2 = fminf(fmaxf(rois[i * 4 + 3], 0.f), IMGSZ);
    bool valid = ((y2 - y1) >= MIN_SIZE) && ((x2 - x1) >= MIN_SIZE);
    float l0 = logits[i * 2 + 0], l1 = logits[i * 2 + 1];
    float m = fmaxf(l0, l1);
    float e0 = expf(l0 - m), e1 = expf(l1 - m);
    float score = valid ? (e1 / (e0 + e1)) : -1.0f;
    unsigned b = __float_as_uint(score);
    unsigned key = (b & 0x80000000u) ? ~b : (b | 0x80000000u);
    g_keys[i] = ((unsigned long long)key << 32) | (unsigned)(~(unsigned)i);
    atomicAdd(&g_hist[key >> 16], 1);
}

// ---------------- stage 2: threshold bin ----------------
__global__ void threshK() {
    __shared__ int suf[1024];
    int t = threadIdx.x;
    int s = 0;
    for (int b = t * 64; b < t * 64 + 64; b++) s += g_hist[b];
    suf[t] = s;
    __syncthreads();
    for (int off = 1; off < 1024; off <<= 1) {
        int v = (t + off < 1024) ? suf[t + off] : 0;
        __syncthreads();
        suf[t] += v;
        __syncthreads();
    }
    int run = (t + 1 < 1024) ? suf[t + 1] : 0;
    for (int b = t * 64 + 63; b >= t * 64; b--) {
        int h = g_hist[b];
        int ge = run + h;
        if (ge >= PRE_NMS && run < PRE_NMS) g_threshBin = b;
        run = ge;
    }
}

// ---------------- stage 3: compact ----------------
__global__ void compactK() {
    int i = blockIdx.x * blockDim.x + threadIdx.x;
    if (i >= N_ROIS) return;
    unsigned long long k = g_keys[i];
    int bin = (int)(k >> 48);
    if (bin >= g_threshBin) {
        int pos = atomicAdd(&g_cnt, 1);
        if (pos < SORT_N) g_cand[pos] = k;
    }
}

// ---------------- stage 4: bitonic sort + emit boxes ----------------
__global__ void sortK(const float* __restrict__ rois) {
    __shared__ unsigned long long s[SORT_N];
    int tid = threadIdx.x;
    int cnt = g_cnt; if (cnt > SORT_N) cnt = SORT_N;
    for (int i = tid; i < SORT_N; i += 1024) s[i] = (i < cnt) ? g_cand[i] : 0ULL;
    __syncthreads();
    for (int k = 2; k <= SORT_N; k <<= 1) {
        for (int j = k >> 1; j > 0; j >>= 1) {
            for (int i = tid; i < SORT_N; i += 1024) {
                int l = i ^ j;
                if (l > i) {
                    unsigned long long a = s[i], b = s[l];
                    bool desc = ((i & k) == 0);
                    bool sw = desc ? (a < b) : (a > b);
                    if (sw) { s[i] = b; s[l] = a; }
                }
            }
            __syncthreads();
        }
    }
    for (int r = tid; r < PRE_NMS; r += 1024) {
        int idx = (int)(~(unsigned)s[r]);
        g_boxes[r * 4 + 0] = fminf(fmaxf(rois[idx * 4 + 0], 0.f), IMGSZ);
        g_boxes[r * 4 + 1] = fminf(fmaxf(rois[idx * 4 + 1], 0.f), IMGSZ);
        g_boxes[r * 4 + 2] = fminf(fmaxf(rois[idx * 4 + 2], 0.f), IMGSZ);
        g_boxes[r * 4 + 3] = fminf(fmaxf(rois[idx * 4 + 3], 0.f), IMGSZ);
    }
}

// ---------------- stage 5: NMS IoU bitmask ----------------
__global__ void nmsMaskK() {
    __shared__ float col[64][4];
    int t = threadIdx.x;
    int cbase = blockIdx.x * 64;
    if (cbase + t < PRE_NMS) {
        col[t][0] = g_boxes[(cbase + t) * 4 + 0];
        col[t][1] = g_boxes[(cbase + t) * 4 + 1];
        col[t][2] = g_boxes[(cbase + t) * 4 + 2];
        col[t][3] = g_boxes[(cbase + t) * 4 + 3];
    } else {
        col[t][0] = col[t][1] = col[t][2] = col[t][3] = 0.f;
    }
    __syncthreads();
    int row = blockIdx.y * 64 + t;
    if (row >= PRE_NMS) return;
    float ry1 = g_boxes[row * 4 + 0], rx1 = g_boxes[row * 4 + 1];
    float ry2 = g_boxes[row * 4 + 2], rx2 = g_boxes[row * 4 + 3];
    float ra = (ry2 - ry1) * (rx2 - rx1);
    unsigned long long bits = 0;
    #pragma unroll 8
    for (int j = 0; j < 64; j++) {
        int c = cbase + j;
        if (c >= PRE_NMS || c == row) continue;
        float ca = (col[j][2] - col[j][0]) * (col[j][3] - col[j][1]);
        float yy1 = fmaxf(ry1, col[j][0]);
        float xx1 = fmaxf(rx1, col[j][1]);
        float yy2 = fminf(ry2, col[j][2]);
        float xx2 = fminf(rx2, col[j][3]);
        float inter = fmaxf(yy2 - yy1, 0.f) * fmaxf(xx2 - xx1, 0.f);
        float iou = inter / (ra + ca - inter + 1e-9f);
        if (iou > IOU_TH) bits |= (1ull << j);
    }
    g_mask[row * 32 + blockIdx.x] = bits;
}

// ---------------- stage 6: NMS scan with cp.async prefetch ring ----------------
__global__ void nmsScanK(float* __restrict__ out) {
    __shared__ __align__(16) unsigned long long ring[64][32];
    __shared__ unsigned char keptFlag[PRE_NMS];
    int lane = threadIdx.x;  // 32 threads
    for (int i = lane; i < PRE_NMS; i += 32) keptFlag[i] = 0;
    uint32_t rb = smem_u32(&ring[0][0]);
    // prologue: prefetch rows 0..63, one commit group per row
    for (int r = 0; r < 64; r++) {
        cpasync8(rb + ((uint32_t)r * 32 + lane) * 8, &g_mask[(size_t)r * 32 + lane]);
        cp_commit();
    }
    __syncwarp();
    unsigned long long remv = 0;
    int cnt = 0;
    for (int i = 0; i < PRE_NMS; i++) {
        unsigned long long w = __shfl_sync(0xffffffffu, remv, i >> 6);
        if (!((w >> (i & 63)) & 1ull)) {
            // committed groups so far = 64 + i; <=48 outstanding => rows <= i+15 done
            cp_wait48();
            remv |= ring[i & 63][lane];
            if (cnt < POST_NMS && lane == 0) { g_keep[cnt] = i; keptFlag[i] = 1; }
            cnt++;
            if (cnt == POST_NMS) break;
        }
        int nf = i + 64;
        if (nf < PRE_NMS)
            cpasync8(rb + ((uint32_t)(nf & 63) * 32 + lane) * 8, &g_mask[(size_t)nf * 32 + lane]);
        cp_commit();
    }
    cp_wait0();
    __syncwarp();
    if (lane == 0 && cnt < POST_NMS) {
        int extras[POST_NMS]; int ne = 0;
        for (int i = 0; i < PRE_NMS && ne < POST_NMS - cnt; i++)
            if (!keptFlag[i]) extras[ne++] = i;
        int merged[POST_NMS]; int a = 0, b = 0;
        for (int o = 0; o < POST_NMS; o++) {
            int va = (a < cnt) ? g_keep[a] : 0x7fffffff;
            int vb = (b < ne) ? extras[b] : 0x7fffffff;
            if (va < vb) { merged[o] = va; a++; } else { merged[o] = vb; b++; }
        }
        for (int o = 0; o < POST_NMS; o++) g_keep[o] = merged[o];
    }
    __syncwarp();
    for (int r = lane; r < POST_NMS; r += 32) {
        int idx = g_keep[r];
        #pragma unroll
        for (int j = 0; j < 4; j++) {
            float v = g_boxes[idx * 4 + j];
            g_roisKept[r * 4 + j] = v;
            out[OFF_ROIS + r * 4 + j] = v;
        }
    }
}

// ---------------- stage 7: transpose CHW -> HWC ----------------
__global__ void transposeK(const float* __restrict__ feat) {
    __shared__ float tile[32][33];
    int p = blockIdx.x * 32 + threadIdx.x;
    int c = blockIdx.y * 32 + threadIdx.y;
    #pragma unroll
    for (int j = 0; j < 32; j += 8)
        if (p < 2500 && (c + j) < FEAT_C)
            tile[threadIdx.y + j][threadIdx.x] = feat[(c + j) * 2500 + p];
    __syncthreads();
    int c2 = blockIdx.y * 32 + threadIdx.x;
    int p2 = blockIdx.x * 32 + threadIdx.y;
    #pragma unroll
    for (int j = 0; j < 32; j += 8)
        if (c2 < FEAT_C && (p2 + j) < 2500)
            g_featT[(p2 + j) * FEAT_C + c2] = tile[threadIdx.x][threadIdx.y + j];
}

// ---------------- stage 8: ROI align (emits fp16) ----------------
__global__ void roiAlignK() {
    int r = blockIdx.x;
    __shared__ float box[4];
    __shared__ int sy0[14], sy1[14], sx0[14], sx1[14];
    __shared__ float sly[14], slx[14];
    int t = threadIdx.x;
    if (t < 4) box[t] = g_roisKept[r * 4 + t] * (1.0f / 16.0f);
    __syncthreads();
    if (t < 28) {
        int d = t / 14, g = t % 14;
        float c1 = d ? box[1] : box[0];
        float c2 = d ? box[3] : box[2];
        float bsz = fmaxf(c2 - c1, 1.0f) * (1.0f / 7.0f);
        float gg = ((float)g + 0.5f) * 0.5f;
        float s = c1 + gg * bsz;
        s = fminf(fmaxf(s, 0.0f), 49.0f);
        float s0 = floorf(s);
        int i0 = (int)s0;
        int i1 = min(i0 + 1, 49);
        float l = s - s0;
        if (d == 0) { sy0[g] = i0; sy1[g] = i1; sly[g] = l; }
        else        { sx0[g] = i0; sx1[g] = i1; slx[g] = l; }
    }
    __syncthreads();
    __half* outp = g_A1 + (size_t)r * D_IN;
    for (int c = t; c < FEAT_C; c += 256) {
        #pragma unroll
        for (int oy = 0; oy < 7; oy++) {
            #pragma unroll
            for (int ox = 0; ox < 7; ox++) {
                float acc = 0.f;
                #pragma unroll
                for (int sy = 0; sy < 2; sy++) {
                    #pragma unroll
                    for (int sx = 0; sx < 2; sx++) {
                        int i = oy * 2 + sy, j = ox * 2 + sx;
                        int y0 = sy0[i], y1 = sy1[i], x0 = sx0[j], x1 = sx1[j];
                        float ly = sly[i], lx = slx[j];
                        const float* f = g_featT;
                        float v00 = f[(y0 * 50 + x0) * FEAT_C + c];
                        float v01 = f[(y0 * 50 + x1) * FEAT_C + c];
                        float v10 = f[(y1 * 50 + x0) * FEAT_C + c];
                        float v11 = f[(y1 * 50 + x1) * FEAT_C + c];
                        acc += (1.f - ly) * ((1.f - lx) * v00 + lx * v01)
                             + ly * ((1.f - lx) * v10 + lx * v11);
                    }
                }
                outp[(oy * 7 + ox) * FEAT_C + c] = __float2half_rn(acc * 0.25f);
            }
        }
    }
}

// ================= HMMA FC kernel (single-term fp16) =================
// part[ksp][128][4096] = A[128,K](fp16) @ B[K,4096](fp32 -> fp16 on the fly)
// CTA: 256 thr (8 warps, 2M x 4N), tile M=128 N=128, K-chunk 64, double buffered.
// smem buffer (32KB): A 128 rows x 128B (64 fp16) SW128; B at +16384:
//   two 64-n halves, each 64 krows x 128B (64 fp16), SW128.
#define FC_KC     64
#define FC_BUF    32768
#define FC_B_OFF  16384
#define SWZ(o) ((o) ^ (((o) >> 3) & 0x70))

template <int PERM>
__global__ __launch_bounds__(256, 2) void fcHmmaK(
    const __half* __restrict__ A, const float* __restrict__ B,
    float* __restrict__ part, int K, int chunksPerCta)
{
    extern __shared__ char smem[];
    uint32_t sb = smem_u32(smem);
    int tid = threadIdx.x, wid = tid >> 5, lane = tid & 31;
    int mw = wid & 1, nw = wid >> 1;
    int n0 = blockIdx.x * 128;
    int ksp = blockIdx.y;
    int kbase = ksp * chunksPerCta * FC_KC;

    float acc[4][4][4] = {};

    int mat = lane >> 3, r8 = lane & 7;
    int rowA = mw * 64 + (mat & 1) * 8 + r8;
    uint32_t aRowOff = (uint32_t)rowA * 128;
    uint32_t aXor = (uint32_t)(rowA & 7) << 4;
    uint32_t aKb = (uint32_t)(mat >> 1) * 16;
    int krow = (mat & 1) * 8 + r8;
    uint32_t bXorBase = (uint32_t)r8 << 4;

    auto stage = [&](int ci, uint32_t base) {
        int k0 = kbase + ci * FC_KC;
        // A: 128 rows x 8 segs x 16B via cp.async
        #pragma unroll
        for (int e = 0; e < 4; e++) {
            int flat = tid + e * 256;
            int seg = flat & 7, row = flat >> 3;
            const __half* src = A + (size_t)row * K + k0 + seg * 8;
            cpasync16(base + SWZ((uint32_t)row * 128 + seg * 16), src);
        }
        // B: 64 krows x 128 n fp32 -> fp16
        #pragma unroll
        for (int e = 0; e < 8; e++) {
            int flat = tid + e * 256;
            int n4 = flat & 31, k = flat >> 5;
            int gk = k0 + k;
            int grow = PERM ? ((gk & 511) * 49 + (gk >> 9)) : gk;
            float4 f = *(const float4*)(B + (size_t)grow * D_H + n0 + n4 * 4);
            uint32_t p0 = h2pack(f.x, f.y);
            uint32_t p1 = h2pack(f.z, f.w);
            uint32_t off = ((n4 >= 16) ? 8192u : 0u) + SWZ((uint32_t)k * 128 + (n4 & 15) * 8);
            sts64(base + FC_B_OFF + off, p0, p1);
        }
        cp_commit();
    };

    stage(0, sb);
    cp_wait0();
    __syncthreads();

    for (int c = 0; c < chunksPerCta; c++) {
        uint32_t buf = sb + (uint32_t)(c & 1) * FC_BUF;
        if (c + 1 < chunksPerCta) stage(c + 1, sb + (uint32_t)((c + 1) & 1) * FC_BUF);

        #pragma unroll
        for (int ks = 0; ks < 4; ks++) {
            uint32_t a16[4][4], b16[2][4];
            #pragma unroll
            for (int ti = 0; ti < 4; ti++)
                ldsm4(a16[ti], buf + aRowOff + (uint32_t)ti * 2048
                               + (((uint32_t)(ks * 32) + aKb) ^ aXor));
            uint32_t bRow = (uint32_t)(ks * 16 + krow) * 128;
            #pragma unroll
            for (int G = 0; G < 2; G++) {
                int ngg = nw * 4 + G * 2 + (mat >> 1);
                uint32_t off = (uint32_t)(ngg >> 3) * 8192 + bRow
                             + (((uint32_t)(ngg & 7) * 16) ^ bXorBase);
                ldsm4t(b16[G], buf + FC_B_OFF + off);
            }
            #pragma unroll
            for (int ti = 0; ti < 4; ti++)
                #pragma unroll
                for (int tj = 0; tj < 4; tj++)
                    mma16816(acc[ti][tj], a16[ti], &b16[tj >> 1][(tj & 1) * 2]);
        }
        cp_wait0();
        __syncthreads();
    }

    // epilogue: write split-K partials
    int g = lane >> 2, t4 = lane & 3;
    float* pbase = part + ((size_t)ksp * 128) * D_H + n0;
    #pragma unroll
    for (int ti = 0; ti < 4; ti++) {
        int m = mw * 64 + ti * 16 + g;
        #pragma unroll
        for (int tj = 0; tj < 4; tj++) {
            int n = nw * 32 + tj * 8 + t4 * 2;
            float2 v0 = make_float2(acc[ti][tj][0], acc[ti][tj][1]);
            float2 v1 = make_float2(acc[ti][tj][2], acc[ti][tj][3]);
            *(float2*)(pbase + (size_t)m * D_H + n) = v0;
            *(float2*)(pbase + (size_t)(m + 8) * D_H + n) = v1;
        }
    }
}

// ---------------- reduce partials ----------------
__global__ void reduce1K(const float* __restrict__ part, const float* __restrict__ bias,
                         __half* __restrict__ oh) {
    int idx = blockIdx.x * blockDim.x + threadIdx.x;
    if (idx >= POST_NMS * D_H) return;
    int n = idx & (D_H - 1);
    float s = bias[n];
    #pragma unroll
    for (int p = 0; p < 8; p++) s += part[p * (POST_NMS * D_H) + idx];
    oh[idx] = __float2half_rn(s);
}

__global__ void reduce2K(const float* __restrict__ part, const float* __restrict__ bias,
                         float* __restrict__ o) {
    int idx = blockIdx.x * blockDim.x + threadIdx.x;
    if (idx >= POST_NMS * D_H) return;
    int n = idx & (D_H - 1);
    float s = bias[n];
    #pragma unroll
    for (int p = 0; p < 8; p++) s += part[p * (POST_NMS * D_H) + idx];
    o[idx] = s;
}

// ---------------- heads: split-K SIMT GEMM ----------------
__global__ __launch_bounds__(256) void headK(
    const float* __restrict__ A, const float* __restrict__ W,
    float* __restrict__ part, int N, int kLen)
{
    __shared__ float As[16][68];
    __shared__ float Bs[16][68];
    int bn = blockIdx.x * 64, bm = blockIdx.y * 64;
    int k0base = blockIdx.z * kLen;
    int tid = threadIdx.x;
    int tx = tid & 15, ty = tid >> 4;
    float acc[4][4] = {};
    for (int k0 = 0; k0 < kLen; k0 += 16) {
        #pragma unroll
        for (int e = 0; e < 4; e++) {
            int flat = tid + e * 256;
            int m = flat >> 4, kk = flat & 15;
            As[kk][m] = A[(bm + m) * D_H + k0base + k0 + kk];
        }
        #pragma unroll
        for (int e = 0; e < 4; e++) {
            int flat = tid + e * 256;
            int kk = flat >> 6, n = flat & 63;
            int gn = bn + n;
            Bs[kk][n] = (gn < N) ? W[(size_t)(k0base + k0 + kk) * N + gn] : 0.0f;
        }
        __syncthreads();
        #pragma unroll
        for (int kk = 0; kk < 16; kk++) {
            float a[4], b[4];
            #pragma unroll
            for (int i = 0; i < 4; i++) a[i] = As[kk][ty * 4 + i];
            #pragma unroll
            for (int j = 0; j < 4; j++) b[j] = Bs[kk][tx * 4 + j];
            #pragma unroll
            for (int i = 0; i < 4; i++)
                #pragma unroll
                for (int j = 0; j < 4; j++)
                    acc[i][j] = fmaf(a[i], b[j], acc[i][j]);
        }
        __syncthreads();
    }
    #pragma unroll
    for (int i = 0; i < 4; i++) {
        int gm = bm + ty * 4 + i;
        #pragma unroll
        for (int j = 0; j < 4; j++) {
            int gn = bn + tx * 4 + j;
            if (gn < N) part[(size_t)blockIdx.z * 128 * N + gm * N + gn] = acc[i][j];
        }
    }
}

__global__ void headRedK(const float* __restrict__ part, const float* __restrict__ bias,
                         float* __restrict__ out, int N) {
    int idx = blockIdx.x * blockDim.x + threadIdx.x;
    if (idx >= 128 * N) return;
    int n = idx % N;
    float s = bias[n];
    #pragma unroll
    for (int p = 0; p < 8; p++) s += part[p * 128 * N + idx];
    out[idx] = s;
}

// ---------------- launcher ----------------
extern "C" void kernel_launch(void* const* d_in, const int* in_sizes, int n_in,
                              void* d_out, int out_size)
{
    const float* features = (const float*)d_in[0];
    const float* rois     = (const float*)d_in[1];
    const float* logits   = (const float*)d_in[2];
    const float* W1 = (const float*)d_in[3];
    const float* b1 = (const float*)d_in[4];
    const float* W2 = (const float*)d_in[5];
    const float* b2 = (const float*)d_in[6];
    const float* Wc = (const float*)d_in[7];
    const float* bc = (const float*)d_in[8];
    const float* Wd = (const float*)d_in[9];
    const float* bd = (const float*)d_in[10];
    float* out = (float*)d_out;

    __half* A1; cudaGetSymbolAddress((void**)&A1, g_A1);
    __half* A2; cudaGetSymbolAddress((void**)&A2, g_A2);
    float* part; cudaGetSymbolAddress((void**)&part, g_part);
    float* h2;   cudaGetSymbolAddress((void**)&h2, g_h2);

    const int SMEM_BYTES = 2 * FC_BUF;  // 64 KB
    cudaFuncSetAttribute(fcHmmaK<1>, cudaFuncAttributeMaxDynamicSharedMemorySize, SMEM_BYTES);
    cudaFuncSetAttribute(fcHmmaK<0>, cudaFuncAttributeMaxDynamicSharedMemorySize, SMEM_BYTES);

    zeroK<<<64, 1024>>>();
    scoreK<<<(N_ROIS + 255) / 256, 256>>>(rois, logits);
    threshK<<<1, 1024>>>();
    compactK<<<(N_ROIS + 255) / 256, 256>>>();
    sortK<<<1, 1024>>>(rois);
    nmsMaskK<<<dim3(32, 32), 64>>>();
    nmsScanK<<<1, 32>>>(out);
    transposeK<<<dim3(79, 16), dim3(32, 8)>>>(features);
    roiAlignK<<<POST_NMS, 256>>>();

    // FC1: K=25088 = 8 ksplits * 49 chunks * 64
    fcHmmaK<1><<<dim3(32, 8), 256, SMEM_BYTES>>>(A1, W1, part, D_IN, 49);
    reduce1K<<<(POST_NMS * D_H + 255) / 256, 256>>>(part, b1, A2);

    // FC2: K=4096 = 8 ksplits * 8 chunks * 64
    fcHmmaK<0><<<dim3(32, 8), 256, SMEM_BYTES>>>(A2, W2, part, D_H, 8);
    reduce2K<<<(POST_NMS * D_H + 255) / 256, 256>>>(part, b2, h2);

    // heads: split-K 8 x 512
    headK<<<dim3(1, 2, 8), 256>>>(h2, Wc, part, NC, 512);
    headRedK<<<(128 * NC + 255) / 256, 256>>>(part, bc, out, NC);
    headK<<<dim3(2, 2, 8), 256>>>(h2, Wd, part + (1 << 21), NC * 4, 512);
    headRedK<<<(128 * NC * 4 + 255) / 256, 256>>>(part + (1 << 21), bd, out + OFF_DELTAS, NC * 4);
}

// round 7
// speedup vs baseline: 8.2297x; 1.2130x over previous
#include <cuda_runtime.h>
#include <cuda_fp16.h>
#include <math.h>
#include <stdint.h>

// ---------------- constants ----------------
#define N_ROIS   22500
#define IMGSZ    800.0f
#define MIN_SIZE 16.0f
#define PRE_NMS  2000
#define POST_NMS 128
#define IOU_TH   0.7f
#define FEAT_C   512
#define FEAT_HW  50
#define D_IN     25088   // 512*7*7
#define D_H      4096
#define NC       21
#define SORT_N   4096

#define OFF_DELTAS 2688
#define OFF_ROIS   13440

// ---------------- device scratch ----------------
__device__ float              g_featT[FEAT_HW * FEAT_HW * FEAT_C];
__device__ __align__(16) __half g_A1[POST_NMS * D_IN];   // pooled, fp16
__device__ __align__(16) __half g_A2[POST_NMS * D_H];    // h1, fp16
__device__ float              g_part[8 * POST_NMS * D_H];   // split-K partials (16MB)
__device__ float              g_h2[POST_NMS * D_H];
__device__ unsigned long long g_keys[N_ROIS];
__device__ int                g_hist[65536];
__device__ int                g_threshBin;
__device__ float              g_boxes[PRE_NMS * 4];
__device__ unsigned long long g_mask[PRE_NMS * 32];
__device__ int                g_keep[POST_NMS];
__device__ float              g_roisKept[POST_NMS * 4];

// ================= helpers =================
__device__ __forceinline__ uint32_t smem_u32(const void* p) {
    uint32_t a;
    asm("{ .reg .u64 t; cvta.to.shared.u64 t, %1; cvt.u32.u64 %0, t; }" : "=r"(a) : "l"(p));
    return a;
}
__device__ __forceinline__ void sts64(uint32_t a, uint32_t w0, uint32_t w1) {
    asm volatile("st.shared.v2.b32 [%0], {%1,%2};" :: "r"(a), "r"(w0), "r"(w1) : "memory");
}
__device__ __forceinline__ void cpasync16(uint32_t saddr, const void* g) {
    asm volatile("cp.async.cg.shared.global [%0], [%1], 16;" :: "r"(saddr), "l"(g) : "memory");
}
__device__ __forceinline__ void cpasync8(uint32_t saddr, const void* g) {
    asm volatile("cp.async.ca.shared.global [%0], [%1], 8;" :: "r"(saddr), "l"(g) : "memory");
}
__device__ __forceinline__ void cp_commit() {
    asm volatile("cp.async.commit_group;" ::: "memory");
}
__device__ __forceinline__ void cp_wait0() {
    asm volatile("cp.async.wait_group 0;" ::: "memory");
}
__device__ __forceinline__ void cp_wait48() {
    asm volatile("cp.async.wait_group 48;" ::: "memory");
}
__device__ __forceinline__ uint32_t h2pack(float a, float b) {
    __half2 h = __floats2half2_rn(a, b);
    return *reinterpret_cast<uint32_t*>(&h);
}
__device__ __forceinline__ void ldsm4(uint32_t* r, uint32_t a) {
    asm volatile("ldmatrix.sync.aligned.m8n8.x4.shared.b16 {%0,%1,%2,%3}, [%4];"
                 : "=r"(r[0]), "=r"(r[1]), "=r"(r[2]), "=r"(r[3]) : "r"(a));
}
__device__ __forceinline__ void ldsm4t(uint32_t* r, uint32_t a) {
    asm volatile("ldmatrix.sync.aligned.m8n8.x4.trans.shared.b16 {%0,%1,%2,%3}, [%4];"
                 : "=r"(r[0]), "=r"(r[1]), "=r"(r[2]), "=r"(r[3]) : "r"(a));
}
__device__ __forceinline__ void mma16816(float* c, const uint32_t* a, const uint32_t* b) {
    asm volatile(
        "mma.sync.aligned.m16n8k16.row.col.f32.f16.f16.f32 "
        "{%0,%1,%2,%3}, {%4,%5,%6,%7}, {%8,%9}, {%0,%1,%2,%3};"
        : "+f"(c[0]), "+f"(c[1]), "+f"(c[2]), "+f"(c[3])
        : "r"(a[0]), "r"(a[1]), "r"(a[2]), "r"(a[3]), "r"(b[0]), "r"(b[1]));
}

// ---------------- stage 0: zero hist + transpose CHW->HWC (independent, fused) ----------------
__global__ void zeroTransK(const float* __restrict__ feat) {
    __shared__ float tile[32][33];
    int b = blockIdx.x, t = threadIdx.x;
    if (b < 256) {
        g_hist[b * 256 + t] = 0;
        return;
    }
    int bb = b - 256;
    int bx = bb % 79, by = bb / 79;
    int tx = t & 31, ty = t >> 5;
    int p = bx * 32 + tx;
    int c = by * 32 + ty;
    #pragma unroll
    for (int j = 0; j < 32; j += 8)
        if (p < 2500 && (c + j) < FEAT_C)
            tile[ty + j][tx] = feat[(c + j) * 2500 + p];
    __syncthreads();
    int c2 = by * 32 + tx;
    int p2 = bx * 32 + ty;
    #pragma unroll
    for (int j = 0; j < 32; j += 8)
        if (c2 < FEAT_C && (p2 + j) < 2500)
            g_featT[(p2 + j) * FEAT_C + c2] = tile[tx][ty + j];
}

// ---------------- stage 1: score + key + histogram ----------------
__global__ void scoreK(const float* __restrict__ rois, const float* __restrict__ logits) {
    int i = blockIdx.x * blockDim.x + threadIdx.x;
    if (i >= N_ROIS) return;
    float y1 = fminf(fmaxf(rois[i * 4 + 0], 0.f), IMGSZ);
    float x1 = fminf(fmaxf(rois[i * 4 + 1], 0.f), IMGSZ);
    float y2 = fminf(fmaxf(rois[i * 4 + 2], 0.f), IMGSZ);
    float x2 = fminf(fmaxf(rois[i * 4 + 3], 0.f), IMGSZ);
    bool valid = ((y2 - y1) >= MIN_SIZE) && ((x2 - x1) >= MIN_SIZE);
    float l0 = logits[i * 2 + 0], l1 = logits[i * 2 + 1];
    float m = fmaxf(l0, l1);
    float e0 = expf(l0 - m), e1 = expf(l1 - m);
    float score = valid ? (e1 / (e0 + e1)) : -1.0f;
    unsigned b = __float_as_uint(score);
    unsigned key = (b & 0x80000000u) ? ~b : (b | 0x80000000u);
    g_keys[i] = ((unsigned long long)key << 32) | (unsigned)(~(unsigned)i);
    atomicAdd(&g_hist[key >> 16], 1);
}

// ---------------- stage 2: threshold bin ----------------
__global__ void threshK() {
    __shared__ int suf[1024];
    int t = threadIdx.x;
    int s = 0;
    for (int b = t * 64; b < t * 64 + 64; b++) s += g_hist[b];
    suf[t] = s;
    __syncthreads();
    for (int off = 1; off < 1024; off <<= 1) {
        int v = (t + off < 1024) ? suf[t + off] : 0;
        __syncthreads();
        suf[t] += v;
        __syncthreads();
    }
    int run = (t + 1 < 1024) ? suf[t + 1] : 0;
    for (int b = t * 64 + 63; b >= t * 64; b--) {
        int h = g_hist[b];
        int ge = run + h;
        if (ge >= PRE_NMS && run < PRE_NMS) g_threshBin = b;
        run = ge;
    }
}

// ---------------- stage 3: compact (fused) + bitonic sort + emit boxes ----------------
__global__ void sortK(const float* __restrict__ rois) {
    __shared__ unsigned long long s[SORT_N];
    __shared__ int scnt;
    int tid = threadIdx.x;
    if (tid == 0) scnt = 0;
    for (int i = tid; i < SORT_N; i += 1024) s[i] = 0ULL;
    __syncthreads();
    int th = g_threshBin;
    for (int i = tid; i < N_ROIS; i += 1024) {
        unsigned long long k = g_keys[i];
        if ((int)(k >> 48) >= th) {
            int p = atomicAdd(&scnt, 1);
            if (p < SORT_N) s[p] = k;
        }
    }
    __syncthreads();
    for (int k = 2; k <= SORT_N; k <<= 1) {
        for (int j = k >> 1; j > 0; j >>= 1) {
            for (int i = tid; i < SORT_N; i += 1024) {
                int l = i ^ j;
                if (l > i) {
                    unsigned long long a = s[i], b = s[l];
                    bool desc = ((i & k) == 0);
                    bool sw = desc ? (a < b) : (a > b);
                    if (sw) { s[i] = b; s[l] = a; }
                }
            }
            __syncthreads();
        }
    }
    for (int r = tid; r < PRE_NMS; r += 1024) {
        int idx = (int)(~(unsigned)s[r]);
        g_boxes[r * 4 + 0] = fminf(fmaxf(rois[idx * 4 + 0], 0.f), IMGSZ);
        g_boxes[r * 4 + 1] = fminf(fmaxf(rois[idx * 4 + 1], 0.f), IMGSZ);
        g_boxes[r * 4 + 2] = fminf(fmaxf(rois[idx * 4 + 2], 0.f), IMGSZ);
        g_boxes[r * 4 + 3] = fminf(fmaxf(rois[idx * 4 + 3], 0.f), IMGSZ);
    }
}

// ---------------- stage 5: NMS IoU bitmask ----------------
__global__ void nmsMaskK() {
    __shared__ float col[64][4];
    int t = threadIdx.x;
    int cbase = blockIdx.x * 64;
    if (cbase + t < PRE_NMS) {
        col[t][0] = g_boxes[(cbase + t) * 4 + 0];
        col[t][1] = g_boxes[(cbase + t) * 4 + 1];
        col[t][2] = g_boxes[(cbase + t) * 4 + 2];
        col[t][3] = g_boxes[(cbase + t) * 4 + 3];
    } else {
        col[t][0] = col[t][1] = col[t][2] = col[t][3] = 0.f;
    }
    __syncthreads();
    int row = blockIdx.y * 64 + t;
    if (row >= PRE_NMS) return;
    float ry1 = g_boxes[row * 4 + 0], rx1 = g_boxes[row * 4 + 1];
    float ry2 = g_boxes[row * 4 + 2], rx2 = g_boxes[row * 4 + 3];
    float ra = (ry2 - ry1) * (rx2 - rx1);
    unsigned long long bits = 0;
    #pragma unroll 8
    for (int j = 0; j < 64; j++) {
        int c = cbase + j;
        if (c >= PRE_NMS || c == row) continue;
        float ca = (col[j][2] - col[j][0]) * (col[j][3] - col[j][1]);
        float yy1 = fmaxf(ry1, col[j][0]);
        float xx1 = fmaxf(rx1, col[j][1]);
        float yy2 = fminf(ry2, col[j][2]);
        float xx2 = fminf(rx2, col[j][3]);
        float inter = fmaxf(yy2 - yy1, 0.f) * fmaxf(xx2 - xx1, 0.f);
        float iou = inter / (ra + ca - inter + 1e-9f);
        if (iou > IOU_TH) bits |= (1ull << j);
    }
    g_mask[row * 32 + blockIdx.x] = bits;
}

// ---------------- stage 6: NMS scan with cp.async prefetch ring ----------------
__global__ void nmsScanK(float* __restrict__ out) {
    __shared__ __align__(16) unsigned long long ring[64][32];
    __shared__ unsigned char keptFlag[PRE_NMS];
    int lane = threadIdx.x;  // 32 threads
    for (int i = lane; i < PRE_NMS; i += 32) keptFlag[i] = 0;
    uint32_t rb = smem_u32(&ring[0][0]);
    for (int r = 0; r < 64; r++) {
        cpasync8(rb + ((uint32_t)r * 32 + lane) * 8, &g_mask[(size_t)r * 32 + lane]);
        cp_commit();
    }
    __syncwarp();
    unsigned long long remv = 0;
    int cnt = 0;
    for (int i = 0; i < PRE_NMS; i++) {
        unsigned long long w = __shfl_sync(0xffffffffu, remv, i >> 6);
        if (!((w >> (i & 63)) & 1ull)) {
            cp_wait48();
            remv |= ring[i & 63][lane];
            if (cnt < POST_NMS && lane == 0) { g_keep[cnt] = i; keptFlag[i] = 1; }
            cnt++;
            if (cnt == POST_NMS) break;
        }
        int nf = i + 64;
        if (nf < PRE_NMS)
            cpasync8(rb + ((uint32_t)(nf & 63) * 32 + lane) * 8, &g_mask[(size_t)nf * 32 + lane]);
        cp_commit();
    }
    cp_wait0();
    __syncwarp();
    if (lane == 0 && cnt < POST_NMS) {
        int extras[POST_NMS]; int ne = 0;
        for (int i = 0; i < PRE_NMS && ne < POST_NMS - cnt; i++)
            if (!keptFlag[i]) extras[ne++] = i;
        int merged[POST_NMS]; int a = 0, b = 0;
        for (int o = 0; o < POST_NMS; o++) {
            int va = (a < cnt) ? g_keep[a] : 0x7fffffff;
            int vb = (b < ne) ? extras[b] : 0x7fffffff;
            if (va < vb) { merged[o] = va; a++; } else { merged[o] = vb; b++; }
        }
        for (int o = 0; o < POST_NMS; o++) g_keep[o] = merged[o];
    }
    __syncwarp();
    for (int r = lane; r < POST_NMS; r += 32) {
        int idx = g_keep[r];
        #pragma unroll
        for (int j = 0; j < 4; j++) {
            float v = g_boxes[idx * 4 + j];
            g_roisKept[r * 4 + j] = v;
            out[OFF_ROIS + r * 4 + j] = v;
        }
    }
}

// ---------------- stage 8: ROI align (emits fp16) ----------------
__global__ void roiAlignK() {
    int r = blockIdx.x;
    __shared__ float box[4];
    __shared__ int sy0[14], sy1[14], sx0[14], sx1[14];
    __shared__ float sly[14], slx[14];
    int t = threadIdx.x;
    if (t < 4) box[t] = g_roisKept[r * 4 + t] * (1.0f / 16.0f);
    __syncthreads();
    if (t < 28) {
        int d = t / 14, g = t % 14;
        float c1 = d ? box[1] : box[0];
        float c2 = d ? box[3] : box[2];
        float bsz = fmaxf(c2 - c1, 1.0f) * (1.0f / 7.0f);
        float gg = ((float)g + 0.5f) * 0.5f;
        float s = c1 + gg * bsz;
        s = fminf(fmaxf(s, 0.0f), 49.0f);
        float s0 = floorf(s);
        int i0 = (int)s0;
        int i1 = min(i0 + 1, 49);
        float l = s - s0;
        if (d == 0) { sy0[g] = i0; sy1[g] = i1; sly[g] = l; }
        else        { sx0[g] = i0; sx1[g] = i1; slx[g] = l; }
    }
    __syncthreads();
    __half* outp = g_A1 + (size_t)r * D_IN;
    for (int c = t; c < FEAT_C; c += 256) {
        #pragma unroll
        for (int oy = 0; oy < 7; oy++) {
            #pragma unroll
            for (int ox = 0; ox < 7; ox++) {
                float acc = 0.f;
                #pragma unroll
                for (int sy = 0; sy < 2; sy++) {
                    #pragma unroll
                    for (int sx = 0; sx < 2; sx++) {
                        int i = oy * 2 + sy, j = ox * 2 + sx;
                        int y0 = sy0[i], y1 = sy1[i], x0 = sx0[j], x1 = sx1[j];
                        float ly = sly[i], lx = slx[j];
                        const float* f = g_featT;
                        float v00 = f[(y0 * 50 + x0) * FEAT_C + c];
                        float v01 = f[(y0 * 50 + x1) * FEAT_C + c];
                        float v10 = f[(y1 * 50 + x0) * FEAT_C + c];
                        float v11 = f[(y1 * 50 + x1) * FEAT_C + c];
                        acc += (1.f - ly) * ((1.f - lx) * v00 + lx * v01)
                             + ly * ((1.f - lx) * v10 + lx * v11);
                    }
                }
                outp[(oy * 7 + ox) * FEAT_C + c] = __float2half_rn(acc * 0.25f);
            }
        }
    }
}

// ================= HMMA FC kernel (fp16, cp.async B staging + smem convert) =================
// part[ksp][128][4096] = A[128,K](fp16) @ B[K,4096](fp32 -> fp16 via smem)
// CTA: 256 thr (8 warps, 2M x 4N), tile M=128 N=128, K-chunk 64.
// smem: A double buf 2x16KB, Bh fp16 16KB (single), Braw fp32 64x528B (single, cp.async).
#define FC_KC     64
#define FC_A1OFF  16384
#define FC_BH     32768
#define FC_BRAW   49152
#define FC_SMEM   (49152 + 64 * 528)   // 82944
#define SWZ(o) ((o) ^ (((o) >> 3) & 0x70))

template <int PERM>
__global__ __launch_bounds__(256, 2) void fcHmmaK(
    const __half* __restrict__ A, const float* __restrict__ B,
    float* __restrict__ part, int K, int chunksPerCta)
{
    extern __shared__ char smem[];
    uint32_t sb = smem_u32(smem);
    int tid = threadIdx.x, wid = tid >> 5, lane = tid & 31;
    int mw = wid & 1, nw = wid >> 1;
    int n0 = blockIdx.x * 128;
    int ksp = blockIdx.y;
    int kbase = ksp * chunksPerCta * FC_KC;

    float acc[4][4][4] = {};

    int mat = lane >> 3, r8 = lane & 7;
    int rowA = mw * 64 + (mat & 1) * 8 + r8;
    uint32_t aRowOff = (uint32_t)rowA * 128;
    uint32_t aXor = (uint32_t)(rowA & 7) << 4;
    uint32_t aKb = (uint32_t)(mat >> 1) * 16;
    int krow = (mat & 1) * 8 + r8;
    uint32_t bXorBase = (uint32_t)r8 << 4;

    // issue cp.async for chunk ci: A into buf (ci&1), B raw fp32 into Braw
    auto stageIssue = [&](int ci) {
        int k0 = kbase + ci * FC_KC;
        uint32_t abuf = sb + ((ci & 1) ? FC_A1OFF : 0);
        #pragma unroll
        for (int e = 0; e < 4; e++) {
            int flat = tid + e * 256;
            int seg = flat & 7, row = flat >> 3;
            cpasync16(abuf + SWZ((uint32_t)row * 128 + seg * 16),
                      A + (size_t)row * K + k0 + seg * 8);
        }
        #pragma unroll
        for (int e = 0; e < 8; e++) {
            int flat = tid + e * 256;
            int row = flat >> 5, c16 = flat & 31;
            int gk = k0 + row;
            int grow = PERM ? ((gk & 511) * 49 + (gk >> 9)) : gk;
            cpasync16(sb + FC_BRAW + (uint32_t)row * 528 + c16 * 16,
                      B + (size_t)grow * D_H + n0 + c16 * 4);
        }
    };

    stageIssue(0);
    cp_commit();

    for (int c = 0; c < chunksPerCta; c++) {
        cp_wait0();
        __syncthreads();
        // convert Braw fp32 -> Bh fp16 (SW128)
        #pragma unroll
        for (int e = 0; e < 8; e++) {
            int flat = tid + e * 256;
            int n4 = flat & 31, k = flat >> 5;
            float4 v = *(const float4*)(smem + FC_BRAW + (uint32_t)k * 528 + n4 * 16);
            uint32_t p0 = h2pack(v.x, v.y);
            uint32_t p1 = h2pack(v.z, v.w);
            uint32_t off = ((n4 >= 16) ? 8192u : 0u) + SWZ((uint32_t)k * 128 + (n4 & 15) * 8);
            sts64(sb + FC_BH + off, p0, p1);
        }
        __syncthreads();
        if (c + 1 < chunksPerCta) stageIssue(c + 1);
        cp_commit();

        uint32_t abase = sb + ((c & 1) ? FC_A1OFF : 0);
        #pragma unroll
        for (int ks = 0; ks < 4; ks++) {
            uint32_t a16[4][4], b16[2][4];
            #pragma unroll
            for (int ti = 0; ti < 4; ti++)
                ldsm4(a16[ti], abase + aRowOff + (uint32_t)ti * 2048
                               + (((uint32_t)(ks * 32) + aKb) ^ aXor));
            uint32_t bRow = (uint32_t)(ks * 16 + krow) * 128;
            #pragma unroll
            for (int G = 0; G < 2; G++) {
                int ngg = nw * 4 + G * 2 + (mat >> 1);
                uint32_t off = (uint32_t)(ngg >> 3) * 8192 + bRow
                             + (((uint32_t)(ngg & 7) * 16) ^ bXorBase);
                ldsm4t(b16[G], sb + FC_BH + off);
            }
            #pragma unroll
            for (int ti = 0; ti < 4; ti++)
                #pragma unroll
                for (int tj = 0; tj < 4; tj++)
                    mma16816(acc[ti][tj], a16[ti], &b16[tj >> 1][(tj & 1) * 2]);
        }
    }

    // epilogue: write split-K partials
    int g = lane >> 2, t4 = lane & 3;
    float* pbase = part + ((size_t)ksp * 128) * D_H + n0;
    #pragma unroll
    for (int ti = 0; ti < 4; ti++) {
        int m = mw * 64 + ti * 16 + g;
        #pragma unroll
        for (int tj = 0; tj < 4; tj++) {
            int n = nw * 32 + tj * 8 + t4 * 2;
            float2 v0 = make_float2(acc[ti][tj][0], acc[ti][tj][1]);
            float2 v1 = make_float2(acc[ti][tj][2], acc[ti][tj][3]);
            *(float2*)(pbase + (size_t)m * D_H + n) = v0;
            *(float2*)(pbase + (size_t)(m + 8) * D_H + n) = v1;
        }
    }
}

// ---------------- reduce partials ----------------
__global__ void reduce1K(const float* __restrict__ part, const float* __restrict__ bias,
                         __half* __restrict__ oh) {
    int idx = blockIdx.x * blockDim.x + threadIdx.x;
    if (idx >= POST_NMS * D_H) return;
    int n = idx & (D_H - 1);
    float s = bias[n];
    #pragma unroll
    for (int p = 0; p < 8; p++) s += part[p * (POST_NMS * D_H) + idx];
    oh[idx] = __float2half_rn(s);
}

__global__ void reduce2K(const float* __restrict__ part, const float* __restrict__ bias,
                         float* __restrict__ o) {
    int idx = blockIdx.x * blockDim.x + threadIdx.x;
    if (idx >= POST_NMS * D_H) return;
    int n = idx & (D_H - 1);
    float s = bias[n];
    #pragma unroll
    for (int p = 0; p < 8; p++) s += part[p * (POST_NMS * D_H) + idx];
    o[idx] = s;
}

// ---------------- heads: fused cls+delta split-K SIMT GEMM ----------------
__global__ __launch_bounds__(256) void headK(
    const float* __restrict__ A, const float* __restrict__ Wc,
    const float* __restrict__ Wd, float* __restrict__ partC,
    float* __restrict__ partD)
{
    __shared__ float As[16][68];
    __shared__ float Bs[16][68];
    const float* W; float* part; int N, bn;
    if (blockIdx.x == 0) { W = Wc; part = partC; N = NC; bn = 0; }
    else { W = Wd; part = partD; N = NC * 4; bn = (blockIdx.x - 1) * 64; }
    int bm = blockIdx.y * 64;
    int kLen = 512;
    int k0base = blockIdx.z * kLen;
    int tid = threadIdx.x;
    int tx = tid & 15, ty = tid >> 4;
    float acc[4][4] = {};
    for (int k0 = 0; k0 < kLen; k0 += 16) {
        #pragma unroll
        for (int e = 0; e < 4; e++) {
            int flat = tid + e * 256;
            int m = flat >> 4, kk = flat & 15;
            As[kk][m] = A[(bm + m) * D_H + k0base + k0 + kk];
        }
        #pragma unroll
        for (int e = 0; e < 4; e++) {
            int flat = tid + e * 256;
            int kk = flat >> 6, n = flat & 63;
            int gn = bn + n;
            Bs[kk][n] = (gn < N) ? W[(size_t)(k0base + k0 + kk) * N + gn] : 0.0f;
        }
        __syncthreads();
        #pragma unroll
        for (int kk = 0; kk < 16; kk++) {
            float a[4], b[4];
            #pragma unroll
            for (int i = 0; i < 4; i++) a[i] = As[kk][ty * 4 + i];
            #pragma unroll
            for (int j = 0; j < 4; j++) b[j] = Bs[kk][tx * 4 + j];
            #pragma unroll
            for (int i = 0; i < 4; i++)
                #pragma unroll
                for (int j = 0; j < 4; j++)
                    acc[i][j] = fmaf(a[i], b[j], acc[i][j]);
        }
        __syncthreads();
    }
    #pragma unroll
    for (int i = 0; i < 4; i++) {
        int gm = bm + ty * 4 + i;
        #pragma unroll
        for (int j = 0; j < 4; j++) {
            int gn = bn + tx * 4 + j;
            if (gn < N) part[(size_t)blockIdx.z * 128 * N + gm * N + gn] = acc[i][j];
        }
    }
}

__global__ void headRedK(const float* __restrict__ partC, const float* __restrict__ partD,
                         const float* __restrict__ bc, const float* __restrict__ bd,
                         float* __restrict__ out) {
    int idx = blockIdx.x * blockDim.x + threadIdx.x;
    if (idx >= 128 * 105) return;
    int r = idx / 105, c = idx % 105;
    if (c < NC) {
        float s = bc[c];
        #pragma unroll
        for (int p = 0; p < 8; p++) s += partC[p * 128 * NC + r * NC + c];
        out[r * NC + c] = s;
    } else {
        int cd = c - NC;
        float s = bd[cd];
        #pragma unroll
        for (int p = 0; p < 8; p++) s += partD[p * 128 * NC * 4 + r * NC * 4 + cd];
        out[OFF_DELTAS + r * NC * 4 + cd] = s;
    }
}

// ---------------- launcher ----------------
extern "C" void kernel_launch(void* const* d_in, const int* in_sizes, int n_in,
                              void* d_out, int out_size)
{
    const float* features = (const float*)d_in[0];
    const float* rois     = (const float*)d_in[1];
    const float* logits   = (const float*)d_in[2];
    const float* W1 = (const float*)d_in[3];
    const float* b1 = (const float*)d_in[4];
    const float* W2 = (const float*)d_in[5];
    const float* b2 = (const float*)d_in[6];
    const float* Wc = (const float*)d_in[7];
    const float* bc = (const float*)d_in[8];
    const float* Wd = (const float*)d_in[9];
    const float* bd = (const float*)d_in[10];
    float* out = (float*)d_out;

    __half* A1; cudaGetSymbolAddress((void**)&A1, g_A1);
    __half* A2; cudaGetSymbolAddress((void**)&A2, g_A2);
    float* part; cudaGetSymbolAddress((void**)&part, g_part);
    float* h2;   cudaGetSymbolAddress((void**)&h2, g_h2);

    cudaFuncSetAttribute(fcHmmaK<1>, cudaFuncAttributeMaxDynamicSharedMemorySize, FC_SMEM);
    cudaFuncSetAttribute(fcHmmaK<0>, cudaFuncAttributeMaxDynamicSharedMemorySize, FC_SMEM);

    zeroTransK<<<256 + 79 * 16, 256>>>(features);
    scoreK<<<(N_ROIS + 255) / 256, 256>>>(rois, logits);
    threshK<<<1, 1024>>>();
    sortK<<<1, 1024>>>(rois);
    nmsMaskK<<<dim3(32, 32), 64>>>();
    nmsScanK<<<1, 32>>>(out);
    roiAlignK<<<POST_NMS, 256>>>();

    // FC1: K=25088 = 8 ksplits * 49 chunks * 64
    fcHmmaK<1><<<dim3(32, 8), 256, FC_SMEM>>>(A1, W1, part, D_IN, 49);
    reduce1K<<<(POST_NMS * D_H + 255) / 256, 256>>>(part, b1, A2);

    // FC2: K=4096 = 8 ksplits * 8 chunks * 64
    fcHmmaK<0><<<dim3(32, 8), 256, FC_SMEM>>>(A2, W2, part, D_H, 8);
    reduce2K<<<(POST_NMS * D_H + 255) / 256, 256>>>(part, b2, h2);

    // heads: fused cls (x=0) + delta (x=1,2), split-K 8 x 512
    headK<<<dim3(3, 2, 8), 256>>>(h2, Wc, Wd, part, part + (1 << 21));
    headRedK<<<(128 * 105 + 255) / 256, 256>>>(part, part + (1 << 21), bc, bd, out);
}